// round 4
// baseline (speedup 1.0000x reference)
#include <cuda_runtime.h>
#include <cuda_bf16.h>
#include <cuda_pipeline.h>
#include <mma.h>
#include <math.h>

using namespace nvcuda;

#define BATCH 4
#define SEQ   1024
#define DIM   4096
#define NH    32
#define NKV   8
#define HD    128
#define NTOK  (BATCH*SEQ)
#define SCALE 0.08838834764831845f

#define BK 32
#define AST (BK + 4)       // 36 floats

// ---------------- scratch ----------------
__device__ float g_Q[(size_t)NTOK * DIM];
__device__ float g_K[(size_t)NTOK * NKV * HD];
__device__ float g_V[(size_t)NTOK * NKV * HD];
__device__ float g_S[(size_t)BATCH * NH * SEQ * SEQ];
__device__ float g_A[(size_t)NTOK * DIM];

// ---------------- TBM x TBN x 32 TF32 wmma GEMM, cp.async double-buffered ------
// 256 threads = 8 warps arranged (TBM/64) x (TBN/64); each warp owns 64x64
// (4x4 wmma 16x16x8 fragments).
// BT=false: B is [K,N] row-major;  BT=true: B is [N,K] row-major (C = A B^T).
template<int TBM, int TBN, bool BT>
__device__ __forceinline__ void gemm_block(const float* __restrict__ A, int lda,
                                           const float* __restrict__ B, int ldb,
                                           float* __restrict__ C, int ldc, int K)
{
    constexpr int BST      = BT ? (BK + 4) : (TBN + 4);
    constexpr int A_STAGE  = TBM * AST;
    constexpr int B_STAGE  = BT ? TBN * BST : BK * BST;
    constexpr int WC       = TBN / 64;           // warps along N
    constexpr int A_ITER   = (TBM * 8) / 256;    // float4 loads per thread
    constexpr int B_ITER   = BT ? (TBN * 8) / 256 : (BK * TBN / 4) / 256;

    extern __shared__ float smem[];
    float* sA[2] = { smem,                smem + A_STAGE };
    float* sB[2] = { smem + 2 * A_STAGE,  smem + 2 * A_STAGE + B_STAGE };

    const int tid  = threadIdx.x;
    const int warp = tid >> 5;
    const int wm   = (warp / WC) * 64;
    const int wn   = (warp % WC) * 64;
    const int bm   = blockIdx.y * TBM;
    const int bn   = blockIdx.x * TBN;

    wmma::fragment<wmma::accumulator, 16, 16, 8, float> acc[4][4];
#pragma unroll
    for (int i = 0; i < 4; i++)
#pragma unroll
        for (int j = 0; j < 4; j++) wmma::fill_fragment(acc[i][j], 0.0f);

    auto load_tile = [&](int st, int k0) {
#pragma unroll
        for (int l = 0; l < A_ITER; l++) {
            int idx = l * 256 + tid;
            int r = idx >> 3, c4 = idx & 7;
            __pipeline_memcpy_async(&sA[st][r * AST + c4 * 4],
                                    &A[(size_t)(bm + r) * lda + k0 + c4 * 4], 16);
        }
        if (BT) {
#pragma unroll
            for (int l = 0; l < B_ITER; l++) {
                int idx = l * 256 + tid;
                int n = idx >> 3, c4 = idx & 7;
                __pipeline_memcpy_async(&sB[st][n * BST + c4 * 4],
                                        &B[(size_t)(bn + n) * ldb + k0 + c4 * 4], 16);
            }
        } else {
#pragma unroll
            for (int l = 0; l < B_ITER; l++) {
                int idx = l * 256 + tid;
                int r = idx / (TBN / 4), c4 = idx % (TBN / 4);
                __pipeline_memcpy_async(&sB[st][r * BST + c4 * 4],
                                        &B[(size_t)(k0 + r) * ldb + bn + c4 * 4], 16);
            }
        }
    };

    const int nt = K / BK;
    load_tile(0, 0);
    __pipeline_commit();

    for (int t = 0; t < nt; t++) {
        if (t + 1 < nt) {
            load_tile((t + 1) & 1, (t + 1) * BK);
            __pipeline_commit();
            __pipeline_wait_prior(1);
        } else {
            __pipeline_wait_prior(0);
        }
        __syncthreads();

        const int st = t & 1;
#pragma unroll
        for (int kk = 0; kk < BK; kk += 8) {
            wmma::fragment<wmma::matrix_a, 16, 16, 8, wmma::precision::tf32, wmma::row_major> af[4];
#pragma unroll
            for (int i = 0; i < 4; i++) {
                wmma::load_matrix_sync(af[i], &sA[st][(wm + i * 16) * AST + kk], AST);
#pragma unroll
                for (int e = 0; e < af[i].num_elements; e++)
                    af[i].x[e] = wmma::__float_to_tf32(af[i].x[e]);
            }
            if (BT) {
                wmma::fragment<wmma::matrix_b, 16, 16, 8, wmma::precision::tf32, wmma::col_major> bf[4];
#pragma unroll
                for (int j = 0; j < 4; j++) {
                    wmma::load_matrix_sync(bf[j], &sB[st][(wn + j * 16) * BST + kk], BST);
#pragma unroll
                    for (int e = 0; e < bf[j].num_elements; e++)
                        bf[j].x[e] = wmma::__float_to_tf32(bf[j].x[e]);
                }
#pragma unroll
                for (int i = 0; i < 4; i++)
#pragma unroll
                    for (int j = 0; j < 4; j++)
                        wmma::mma_sync(acc[i][j], af[i], bf[j], acc[i][j]);
            } else {
                wmma::fragment<wmma::matrix_b, 16, 16, 8, wmma::precision::tf32, wmma::row_major> bf[4];
#pragma unroll
                for (int j = 0; j < 4; j++) {
                    wmma::load_matrix_sync(bf[j], &sB[st][kk * BST + wn + j * 16], BST);
#pragma unroll
                    for (int e = 0; e < bf[j].num_elements; e++)
                        bf[j].x[e] = wmma::__float_to_tf32(bf[j].x[e]);
                }
#pragma unroll
                for (int i = 0; i < 4; i++)
#pragma unroll
                    for (int j = 0; j < 4; j++)
                        wmma::mma_sync(acc[i][j], af[i], bf[j], acc[i][j]);
            }
        }
        __syncthreads();
    }

#pragma unroll
    for (int i = 0; i < 4; i++)
#pragma unroll
        for (int j = 0; j < 4; j++)
            wmma::store_matrix_sync(&C[(size_t)(bm + wm + i * 16) * ldc + bn + wn + j * 16],
                                    acc[i][j], ldc, wmma::mem_row_major);
}

// smem byte sizes (host mirrors of device constants)
template<int TBM, int TBN, bool BT>
constexpr int smem_bytes() {
    constexpr int BST = BT ? (BK + 4) : (TBN + 4);
    constexpr int B_STAGE = BT ? TBN * BST : BK * BST;
    return (2 * TBM * AST + 2 * B_STAGE) * 4;
}

// ---------------- kernels ----------------
__global__ void __launch_bounds__(256, 1) k_gemm_q(const float* __restrict__ x, const float* __restrict__ w) {
    gemm_block<128, 256, false>(x, DIM, w, DIM, g_Q, DIM, DIM);
}
__global__ void __launch_bounds__(256, 1) k_gemm_k(const float* __restrict__ x, const float* __restrict__ w) {
    gemm_block<128, 256, false>(x, DIM, w, NKV * HD, g_K, NKV * HD, DIM);
}
__global__ void __launch_bounds__(256, 1) k_gemm_v(const float* __restrict__ x, const float* __restrict__ w) {
    gemm_block<128, 256, false>(x, DIM, w, NKV * HD, g_V, NKV * HD, DIM);
}
__global__ void __launch_bounds__(256, 1) k_gemm_o(const float* __restrict__ w, float* __restrict__ out) {
    gemm_block<128, 256, false>(g_A, DIM, w, DIM, out, DIM, DIM);
}

__global__ void __launch_bounds__(256, 1) k_score() {
    int z = blockIdx.z;
    int b = z >> 5, h = z & 31, kvh = h >> 2;
    const float* A = g_Q + (size_t)b * SEQ * DIM + h * HD;
    const float* B = g_K + (size_t)b * SEQ * (NKV * HD) + kvh * HD;
    float*       C = g_S + (size_t)z * SEQ * SEQ;
    gemm_block<128, 256, true>(A, DIM, B, NKV * HD, C, SEQ, HD);
}

__global__ void __launch_bounds__(256, 1) k_pv() {
    int z = blockIdx.z;
    int b = z >> 5, h = z & 31, kvh = h >> 2;
    const float* A = g_S + (size_t)z * SEQ * SEQ;
    const float* B = g_V + (size_t)b * SEQ * (NKV * HD) + kvh * HD;
    float*       C = g_A + (size_t)b * SEQ * DIM + h * HD;
    gemm_block<256, 128, false>(A, SEQ, B, NKV * HD, C, DIM, SEQ);
}

// ---------------- RoPE ----------------
__device__ __forceinline__ void rope_apply(float* t, const float* __restrict__ cs,
                                           const float* __restrict__ sn, int nh)
{
    int idx = blockIdx.x * 256 + threadIdx.x;
    int i   = idx & 63;
    int th  = idx >> 6;
    int s   = (th / nh) & (SEQ - 1);
    float c  = cs[s * 64 + i];
    float si = sn[s * 64 + i];
    size_t off = (size_t)th * HD + 2 * i;
    float v0 = t[off], v1 = t[off + 1];
    t[off]     = v0 * c - v1 * si;
    t[off + 1] = v0 * si + v1 * c;
}
__global__ void k_rope_q(const float* __restrict__ cs, const float* __restrict__ sn) {
    rope_apply(g_Q, cs, sn, NH);
}
__global__ void k_rope_k(const float* __restrict__ cs, const float* __restrict__ sn) {
    rope_apply(g_K, cs, sn, NKV);
}

// ---------------- softmax ----------------
__global__ void k_softmax() {
    size_t row = blockIdx.x;
    float* p = g_S + row * SEQ;
    int tid = threadIdx.x;
    int lane = tid & 31, warp = tid >> 5;

    float v[8];
    float m = -1e30f;
#pragma unroll
    for (int i = 0; i < 8; i++) { v[i] = p[tid + i * 128] * SCALE; m = fmaxf(m, v[i]); }
#pragma unroll
    for (int o = 16; o; o >>= 1) m = fmaxf(m, __shfl_xor_sync(0xffffffffu, m, o));
    __shared__ float sm[4];
    if (!lane) sm[warp] = m;
    __syncthreads();
    m = fmaxf(fmaxf(sm[0], sm[1]), fmaxf(sm[2], sm[3]));

    float sum = 0.0f;
#pragma unroll
    for (int i = 0; i < 8; i++) { v[i] = __expf(v[i] - m); sum += v[i]; }
#pragma unroll
    for (int o = 16; o; o >>= 1) sum += __shfl_xor_sync(0xffffffffu, sum, o);
    __shared__ float ss[4];
    if (!lane) ss[warp] = sum;
    __syncthreads();
    sum = ss[0] + ss[1] + ss[2] + ss[3];

    float inv = 1.0f / sum;
#pragma unroll
    for (int i = 0; i < 8; i++) p[tid + i * 128] = v[i] * inv;
}

// ---------------- launch ----------------
extern "C" void kernel_launch(void* const* d_in, const int* in_sizes, int n_in,
                              void* d_out, int out_size)
{
    const float* x  = (const float*)d_in[0];
    const float* fc = (const float*)d_in[1];
    const float* fs = (const float*)d_in[2];
    const float* wq = (const float*)d_in[3];
    const float* wk = (const float*)d_in[4];
    const float* wv = (const float*)d_in[5];
    const float* wo = (const float*)d_in[6];
    float* out = (float*)d_out;

    constexpr int SM_NN = smem_bytes<128, 256, false>();
    constexpr int SM_BT = smem_bytes<128, 256, true>();
    constexpr int SM_PV = smem_bytes<256, 128, false>();

    static bool attr_done = false;
    if (!attr_done) {
        cudaFuncSetAttribute(k_gemm_q, cudaFuncAttributeMaxDynamicSharedMemorySize, SM_NN);
        cudaFuncSetAttribute(k_gemm_k, cudaFuncAttributeMaxDynamicSharedMemorySize, SM_NN);
        cudaFuncSetAttribute(k_gemm_v, cudaFuncAttributeMaxDynamicSharedMemorySize, SM_NN);
        cudaFuncSetAttribute(k_gemm_o, cudaFuncAttributeMaxDynamicSharedMemorySize, SM_NN);
        cudaFuncSetAttribute(k_score,  cudaFuncAttributeMaxDynamicSharedMemorySize, SM_BT);
        cudaFuncSetAttribute(k_pv,     cudaFuncAttributeMaxDynamicSharedMemorySize, SM_PV);
        attr_done = true;
    }

    dim3 blk(256);

    k_gemm_q<<<dim3(DIM / 256, NTOK / 128), blk, SM_NN>>>(x, wq);
    k_gemm_k<<<dim3((NKV * HD) / 256, NTOK / 128), blk, SM_NN>>>(x, wk);
    k_gemm_v<<<dim3((NKV * HD) / 256, NTOK / 128), blk, SM_NN>>>(x, wv);

    k_rope_q<<<(BATCH * SEQ * NH * 64) / 256, 256>>>(fc, fs);
    k_rope_k<<<(BATCH * SEQ * NKV * 64) / 256, 256>>>(fc, fs);

    k_score<<<dim3(SEQ / 256, SEQ / 128, BATCH * NH), blk, SM_BT>>>();
    k_softmax<<<BATCH * NH * SEQ, 128>>>();
    k_pv<<<dim3(HD / 128, SEQ / 256, BATCH * NH), blk, SM_PV>>>();

    k_gemm_o<<<dim3(DIM / 256, DIM / 128), blk, SM_NN>>>(wo, out);
}

// round 5
// speedup vs baseline: 1.0502x; 1.0502x over previous
#include <cuda_runtime.h>
#include <cuda_bf16.h>
#include <cuda_pipeline.h>
#include <mma.h>
#include <math.h>

using namespace nvcuda;

#define BATCH 4
#define SEQ   1024
#define DIM   4096
#define NH    32
#define NKV   8
#define HD    128
#define NTOK  (BATCH*SEQ)
#define SCALE 0.08838834764831845f

#define BK  32
#define TB  128
#define AST (BK + 4)       // 36

// ---------------- scratch ----------------
__device__ float g_Q[(size_t)NTOK * DIM];
__device__ float g_K[(size_t)NTOK * NKV * HD];
__device__ float g_V[(size_t)NTOK * NKV * HD];
__device__ float g_S[(size_t)BATCH * NH * SEQ * SEQ];
__device__ float g_A[(size_t)NTOK * DIM];
// tf32-rounded copies of inputs
__device__ float g_x [(size_t)NTOK * DIM];
__device__ float g_wq[(size_t)DIM * DIM];
__device__ float g_wk[(size_t)DIM * NKV * HD];
__device__ float g_wv[(size_t)DIM * NKV * HD];
__device__ float g_wo[(size_t)DIM * DIM];

__device__ __forceinline__ float tf32r(float x) { return wmma::__float_to_tf32(x); }

// ---------------- 128x128x32 TF32 wmma GEMM, cp.async double-buffered ----------
// All operands assumed ALREADY tf32-rounded in memory -> no cvt in mainloop.
// 256 threads = 8 warps in 4(m) x 2(n); warp tile 32x64 = 2x4 wmma 16x16x8.
// BT=false: B [K,N] row-major.  BT=true: B [N,K] row-major (C = A B^T).
// ROUND: tf32-round accumulators before store (for tensors consumed by later GEMMs).
template<bool BT, bool ROUND>
__device__ __forceinline__ void gemm_block(const float* __restrict__ A, int lda,
                                           const float* __restrict__ B, int ldb,
                                           float* __restrict__ C, int ldc, int K)
{
    constexpr int BST     = BT ? (BK + 4) : (TB + 4);       // 36 or 132
    constexpr int A_STAGE = TB * AST;                        // 4608
    constexpr int B_STAGE = BT ? TB * BST : BK * BST;        // 4608 or 4224

    extern __shared__ float smem[];
    float* sA[2] = { smem,               smem + A_STAGE };
    float* sB[2] = { smem + 2 * A_STAGE, smem + 2 * A_STAGE + B_STAGE };

    const int tid  = threadIdx.x;
    const int warp = tid >> 5;
    const int wm   = (warp >> 1) * 32;
    const int wn   = (warp & 1) * 64;
    const int bm   = blockIdx.y * TB;
    const int bn   = blockIdx.x * TB;

    wmma::fragment<wmma::accumulator, 16, 16, 8, float> acc[2][4];
#pragma unroll
    for (int i = 0; i < 2; i++)
#pragma unroll
        for (int j = 0; j < 4; j++) wmma::fill_fragment(acc[i][j], 0.0f);

    auto load_tile = [&](int st, int k0) {
        // A: 128 rows x 32 cols = 1024 float4 -> 4/thread
#pragma unroll
        for (int l = 0; l < 4; l++) {
            int idx = l * 256 + tid;
            int r = idx >> 3, c4 = idx & 7;
            __pipeline_memcpy_async(&sA[st][r * AST + c4 * 4],
                                    &A[(size_t)(bm + r) * lda + k0 + c4 * 4], 16);
        }
        if (BT) {
#pragma unroll
            for (int l = 0; l < 4; l++) {
                int idx = l * 256 + tid;
                int n = idx >> 3, c4 = idx & 7;
                __pipeline_memcpy_async(&sB[st][n * BST + c4 * 4],
                                        &B[(size_t)(bn + n) * ldb + k0 + c4 * 4], 16);
            }
        } else {
            // 32 rows x 128 cols = 1024 float4
#pragma unroll
            for (int l = 0; l < 4; l++) {
                int idx = l * 256 + tid;
                int r = idx >> 5, c4 = idx & 31;
                __pipeline_memcpy_async(&sB[st][r * BST + c4 * 4],
                                        &B[(size_t)(k0 + r) * ldb + bn + c4 * 4], 16);
            }
        }
    };

    const int nt = K / BK;
    load_tile(0, 0);
    __pipeline_commit();

    for (int t = 0; t < nt; t++) {
        if (t + 1 < nt) {
            load_tile((t + 1) & 1, (t + 1) * BK);
            __pipeline_commit();
            __pipeline_wait_prior(1);
        } else {
            __pipeline_wait_prior(0);
        }
        __syncthreads();

        const int st = t & 1;
#pragma unroll
        for (int kk = 0; kk < BK; kk += 8) {
            wmma::fragment<wmma::matrix_a, 16, 16, 8, wmma::precision::tf32, wmma::row_major> af[2];
#pragma unroll
            for (int i = 0; i < 2; i++)
                wmma::load_matrix_sync(af[i], &sA[st][(wm + i * 16) * AST + kk], AST);
            if (BT) {
                wmma::fragment<wmma::matrix_b, 16, 16, 8, wmma::precision::tf32, wmma::col_major> bf[4];
#pragma unroll
                for (int j = 0; j < 4; j++)
                    wmma::load_matrix_sync(bf[j], &sB[st][(wn + j * 16) * BST + kk], BST);
#pragma unroll
                for (int i = 0; i < 2; i++)
#pragma unroll
                    for (int j = 0; j < 4; j++)
                        wmma::mma_sync(acc[i][j], af[i], bf[j], acc[i][j]);
            } else {
                wmma::fragment<wmma::matrix_b, 16, 16, 8, wmma::precision::tf32, wmma::row_major> bf[4];
#pragma unroll
                for (int j = 0; j < 4; j++)
                    wmma::load_matrix_sync(bf[j], &sB[st][kk * BST + wn + j * 16], BST);
#pragma unroll
                for (int i = 0; i < 2; i++)
#pragma unroll
                    for (int j = 0; j < 4; j++)
                        wmma::mma_sync(acc[i][j], af[i], bf[j], acc[i][j]);
            }
        }
        __syncthreads();
    }

#pragma unroll
    for (int i = 0; i < 2; i++)
#pragma unroll
        for (int j = 0; j < 4; j++) {
            if (ROUND)
#pragma unroll
                for (int e = 0; e < acc[i][j].num_elements; e++)
                    acc[i][j].x[e] = tf32r(acc[i][j].x[e]);
            wmma::store_matrix_sync(&C[(size_t)(bm + wm + i * 16) * ldc + bn + wn + j * 16],
                                    acc[i][j], ldc, wmma::mem_row_major);
        }
}

template<bool BT>
constexpr int smem_bytes() {
    constexpr int BST = BT ? (BK + 4) : (TB + 4);
    constexpr int B_STAGE = BT ? TB * BST : BK * BST;
    return (2 * TB * AST + 2 * B_STAGE) * 4;
}

// ---------------- tf32 pre-round pass ----------------
__global__ void k_round(const float4* __restrict__ in, float4* __restrict__ out, int n4) {
    for (int i = blockIdx.x * 256 + threadIdx.x; i < n4; i += gridDim.x * 256) {
        float4 v = in[i];
        v.x = tf32r(v.x); v.y = tf32r(v.y); v.z = tf32r(v.z); v.w = tf32r(v.w);
        out[i] = v;
    }
}

// ---------------- GEMM kernels ----------------
__global__ void __launch_bounds__(256, 2) k_gemm_q(const float* __restrict__ x, const float* __restrict__ w) {
    gemm_block<false, true>(x, DIM, w, DIM, g_Q, DIM, DIM);
}
__global__ void __launch_bounds__(256, 2) k_gemm_k(const float* __restrict__ x, const float* __restrict__ w) {
    gemm_block<false, true>(x, DIM, w, NKV * HD, g_K, NKV * HD, DIM);
}
__global__ void __launch_bounds__(256, 2) k_gemm_v(const float* __restrict__ x, const float* __restrict__ w) {
    gemm_block<false, true>(x, DIM, w, NKV * HD, g_V, NKV * HD, DIM);
}
__global__ void __launch_bounds__(256, 2) k_gemm_o(const float* __restrict__ w, float* __restrict__ out) {
    gemm_block<false, false>(g_A, DIM, w, DIM, out, DIM, DIM);
}

__global__ void __launch_bounds__(256, 2) k_score() {
    int z = blockIdx.z;
    int b = z >> 5, h = z & 31, kvh = h >> 2;
    const float* A = g_Q + (size_t)b * SEQ * DIM + h * HD;
    const float* B = g_K + (size_t)b * SEQ * (NKV * HD) + kvh * HD;
    float*       C = g_S + (size_t)z * SEQ * SEQ;
    gemm_block<true, false>(A, DIM, B, NKV * HD, C, SEQ, HD);
}

__global__ void __launch_bounds__(256, 2) k_pv() {
    int z = blockIdx.z;
    int b = z >> 5, h = z & 31, kvh = h >> 2;
    const float* A = g_S + (size_t)z * SEQ * SEQ;
    const float* B = g_V + (size_t)b * SEQ * (NKV * HD) + kvh * HD;
    float*       C = g_A + (size_t)b * SEQ * DIM + h * HD;
    gemm_block<false, true>(A, SEQ, B, NKV * HD, C, DIM, SEQ);
}

// ---------------- RoPE (re-rounds its outputs to tf32) ----------------
__device__ __forceinline__ void rope_apply(float* t, const float* __restrict__ cs,
                                           const float* __restrict__ sn, int nh)
{
    int idx = blockIdx.x * 256 + threadIdx.x;
    int i   = idx & 63;
    int th  = idx >> 6;
    int s   = (th / nh) & (SEQ - 1);
    float c  = cs[s * 64 + i];
    float si = sn[s * 64 + i];
    size_t off = (size_t)th * HD + 2 * i;
    float v0 = t[off], v1 = t[off + 1];
    t[off]     = tf32r(v0 * c - v1 * si);
    t[off + 1] = tf32r(v0 * si + v1 * c);
}
__global__ void k_rope_q(const float* __restrict__ cs, const float* __restrict__ sn) {
    rope_apply(g_Q, cs, sn, NH);
}
__global__ void k_rope_k(const float* __restrict__ cs, const float* __restrict__ sn) {
    rope_apply(g_K, cs, sn, NKV);
}

// ---------------- softmax (writes tf32-rounded probs) ----------------
__global__ void k_softmax() {
    size_t row = blockIdx.x;
    float* p = g_S + row * SEQ;
    int tid = threadIdx.x;
    int lane = tid & 31, warp = tid >> 5;

    float v[8];
    float m = -1e30f;
#pragma unroll
    for (int i = 0; i < 8; i++) { v[i] = p[tid + i * 128] * SCALE; m = fmaxf(m, v[i]); }
#pragma unroll
    for (int o = 16; o; o >>= 1) m = fmaxf(m, __shfl_xor_sync(0xffffffffu, m, o));
    __shared__ float sm[4];
    if (!lane) sm[warp] = m;
    __syncthreads();
    m = fmaxf(fmaxf(sm[0], sm[1]), fmaxf(sm[2], sm[3]));

    float sum = 0.0f;
#pragma unroll
    for (int i = 0; i < 8; i++) { v[i] = __expf(v[i] - m); sum += v[i]; }
#pragma unroll
    for (int o = 16; o; o >>= 1) sum += __shfl_xor_sync(0xffffffffu, sum, o);
    __shared__ float ss[4];
    if (!lane) ss[warp] = sum;
    __syncthreads();
    sum = ss[0] + ss[1] + ss[2] + ss[3];

    float inv = 1.0f / sum;
#pragma unroll
    for (int i = 0; i < 8; i++) p[tid + i * 128] = tf32r(v[i] * inv);
}

// ---------------- launch ----------------
extern "C" void kernel_launch(void* const* d_in, const int* in_sizes, int n_in,
                              void* d_out, int out_size)
{
    const float* x  = (const float*)d_in[0];
    const float* fc = (const float*)d_in[1];
    const float* fs = (const float*)d_in[2];
    const float* wq = (const float*)d_in[3];
    const float* wk = (const float*)d_in[4];
    const float* wv = (const float*)d_in[5];
    const float* wo = (const float*)d_in[6];
    float* out = (float*)d_out;

    constexpr int SM_NN = smem_bytes<false>();
    constexpr int SM_BT = smem_bytes<true>();

    static bool attr_done = false;
    if (!attr_done) {
        cudaFuncSetAttribute(k_gemm_q, cudaFuncAttributeMaxDynamicSharedMemorySize, SM_NN);
        cudaFuncSetAttribute(k_gemm_k, cudaFuncAttributeMaxDynamicSharedMemorySize, SM_NN);
        cudaFuncSetAttribute(k_gemm_v, cudaFuncAttributeMaxDynamicSharedMemorySize, SM_NN);
        cudaFuncSetAttribute(k_gemm_o, cudaFuncAttributeMaxDynamicSharedMemorySize, SM_NN);
        cudaFuncSetAttribute(k_score,  cudaFuncAttributeMaxDynamicSharedMemorySize, SM_BT);
        cudaFuncSetAttribute(k_pv,     cudaFuncAttributeMaxDynamicSharedMemorySize, SM_NN);
        attr_done = true;
    }

    // device pointers to scratch globals (host-side address fetch is capture-safe: no-op here;
    // use cudaMemcpyToSymbol-free approach via kernels referencing globals directly)
    // tf32 pre-rounding of all GEMM inputs
    float* gx;  cudaGetSymbolAddress((void**)&gx,  g_x);
    float* gwq; cudaGetSymbolAddress((void**)&gwq, g_wq);
    float* gwk; cudaGetSymbolAddress((void**)&gwk, g_wk);
    float* gwv; cudaGetSymbolAddress((void**)&gwv, g_wv);
    float* gwo; cudaGetSymbolAddress((void**)&gwo, g_wo);

    k_round<<<2048, 256>>>((const float4*)x,  (float4*)gx,  NTOK * DIM / 4);
    k_round<<<2048, 256>>>((const float4*)wq, (float4*)gwq, DIM * DIM / 4);
    k_round<<<1024, 256>>>((const float4*)wk, (float4*)gwk, DIM * NKV * HD / 4);
    k_round<<<1024, 256>>>((const float4*)wv, (float4*)gwv, DIM * NKV * HD / 4);
    k_round<<<2048, 256>>>((const float4*)wo, (float4*)gwo, DIM * DIM / 4);

    dim3 blk(256);

    k_gemm_q<<<dim3(DIM / TB, NTOK / TB), blk, SM_NN>>>(gx, gwq);
    k_gemm_k<<<dim3((NKV * HD) / TB, NTOK / TB), blk, SM_NN>>>(gx, gwk);
    k_gemm_v<<<dim3((NKV * HD) / TB, NTOK / TB), blk, SM_NN>>>(gx, gwv);

    k_rope_q<<<(BATCH * SEQ * NH * 64) / 256, 256>>>(fc, fs);
    k_rope_k<<<(BATCH * SEQ * NKV * 64) / 256, 256>>>(fc, fs);

    k_score<<<dim3(SEQ / TB, SEQ / TB, BATCH * NH), blk, SM_BT>>>();
    k_softmax<<<BATCH * NH * SEQ, 128>>>();
    k_pv<<<dim3(HD / TB, SEQ / TB, BATCH * NH), blk, SM_NN>>>();

    k_gemm_o<<<dim3(DIM / TB, DIM / TB), blk, SM_NN>>>(gwo, out);
}

// round 10
// speedup vs baseline: 3.3822x; 3.2206x over previous
#include <cuda_runtime.h>
#include <cuda_fp16.h>
#include <cuda_pipeline.h>
#include <mma.h>
#include <math.h>

using namespace nvcuda;

#define BATCH 4
#define SEQ   1024
#define DIM   4096
#define NH    32
#define NKV   8
#define HD    128
#define KVD   (NKV*HD)            // 1024
#define NTOK  (BATCH*SEQ)         // 4096
#define SCALE 0.08838834764831845f

#define BK   64                   // halves per k-chunk (128B rows)
#define STR  72                   // smem row stride in halves (144B, LDSM conflict-free)

typedef __half half_t;

// ---------------- scratch (device globals) ----------------
__device__ half_t g_xh [(size_t)NTOK * DIM];
__device__ half_t g_wqt[(size_t)DIM * DIM];     // [N,K] transposed
__device__ half_t g_wkt[(size_t)KVD * DIM];
__device__ half_t g_wvt[(size_t)KVD * DIM];
__device__ half_t g_wot[(size_t)DIM * DIM];
__device__ float  g_Qf [(size_t)NTOK * DIM];
__device__ float  g_Kf [(size_t)NTOK * KVD];
__device__ float  g_Vf [(size_t)NTOK * KVD];
__device__ half_t g_Qh [(size_t)NTOK * DIM];
__device__ half_t g_Kh [(size_t)NTOK * KVD];
__device__ half_t g_Vt [(size_t)BATCH * KVD * SEQ];   // [b, kv*d, s]
__device__ float  g_S  [(size_t)BATCH * NH * SEQ * SEQ];
__device__ half_t g_P  [(size_t)BATCH * NH * SEQ * SEQ];
__device__ float  g_Af [(size_t)NTOK * DIM];
__device__ half_t g_Ah [(size_t)NTOK * DIM];

// ---------------- fp16 wmma GEMM: C[M,N] = A @ B^T, 128x128 CTA tile ----------
// A [M,K] row-major fp16, B [N,K] row-major fp16, C fp32.
// 256 threads = 8 warps (4m x 2n); warp tile 32x64 = 2x4 wmma m16n16k16.
// cp.async double-buffered, BK=64 halves.
__device__ __forceinline__ void gemm_hf(const half_t* __restrict__ A, int lda,
                                        const half_t* __restrict__ B, int ldb,
                                        float* __restrict__ C, int ldc, int K,
                                        int bm, int bn)
{
    extern __shared__ half_t sm[];
    half_t* sA[2] = { sm,               sm + 128 * STR };
    half_t* sB[2] = { sm + 2 * 128 * STR, sm + 3 * 128 * STR };

    const int tid  = threadIdx.x;
    const int warp = tid >> 5;
    const int wm   = (warp >> 1) * 32;
    const int wn   = (warp & 1) * 64;

    wmma::fragment<wmma::accumulator, 16, 16, 16, float> acc[2][4];
#pragma unroll
    for (int i = 0; i < 2; i++)
#pragma unroll
        for (int j = 0; j < 4; j++) wmma::fill_fragment(acc[i][j], 0.0f);

    // per stage: A 128 rows x 64 halves = 1024 x 16B chunks (A+B) -> 4 each / thread
    auto load_tile = [&](int st, int k0) {
#pragma unroll
        for (int l = 0; l < 4; l++) {
            int idx = l * 256 + tid;
            int r = idx >> 3, c8 = idx & 7;
            __pipeline_memcpy_async(&sA[st][r * STR + c8 * 8],
                                    &A[(size_t)(bm + r) * lda + k0 + c8 * 8], 16);
            __pipeline_memcpy_async(&sB[st][r * STR + c8 * 8],
                                    &B[(size_t)(bn + r) * ldb + k0 + c8 * 8], 16);
        }
    };

    const int nt = K / BK;
    load_tile(0, 0);
    __pipeline_commit();

    for (int t = 0; t < nt; t++) {
        if (t + 1 < nt) {
            load_tile((t + 1) & 1, (t + 1) * BK);
            __pipeline_commit();
            __pipeline_wait_prior(1);
        } else {
            __pipeline_wait_prior(0);
        }
        __syncthreads();

        const int st = t & 1;
#pragma unroll
        for (int kk = 0; kk < BK; kk += 16) {
            wmma::fragment<wmma::matrix_a, 16, 16, 16, half_t, wmma::row_major> af[2];
#pragma unroll
            for (int i = 0; i < 2; i++)
                wmma::load_matrix_sync(af[i], &sA[st][(wm + i * 16) * STR + kk], STR);
            wmma::fragment<wmma::matrix_b, 16, 16, 16, half_t, wmma::col_major> bf[4];
#pragma unroll
            for (int j = 0; j < 4; j++)
                wmma::load_matrix_sync(bf[j], &sB[st][(wn + j * 16) * STR + kk], STR);
#pragma unroll
            for (int i = 0; i < 2; i++)
#pragma unroll
                for (int j = 0; j < 4; j++)
                    wmma::mma_sync(acc[i][j], af[i], bf[j], acc[i][j]);
        }
        __syncthreads();
    }

#pragma unroll
    for (int i = 0; i < 2; i++)
#pragma unroll
        for (int j = 0; j < 4; j++)
            wmma::store_matrix_sync(&C[(size_t)(bm + wm + i * 16) * ldc + bn + wn + j * 16],
                                    acc[i][j], ldc, wmma::mem_row_major);
}

#define SMEM_HF (4 * 128 * STR * (int)sizeof(half_t))   // 73728 B

// ---------------- GEMM wrapper kernels ----------------
__global__ void __launch_bounds__(256, 2) k_proj(const half_t* A, const half_t* B,
                                                 float* C, int lda, int ldb, int ldc, int K)
{
    gemm_hf(A, lda, B, ldb, C, ldc, K, blockIdx.y * 128, blockIdx.x * 128);
}

__global__ void __launch_bounds__(256, 2) k_score() {
    int z = blockIdx.z;
    int b = z >> 5, h = z & 31, kvh = h >> 2;
    const half_t* A = g_Qh + (size_t)b * SEQ * DIM + h * HD;
    const half_t* B = g_Kh + (size_t)b * SEQ * KVD + kvh * HD;
    float* C = g_S + (size_t)z * SEQ * SEQ;
    gemm_hf(A, DIM, B, KVD, C, SEQ, HD, blockIdx.y * 128, blockIdx.x * 128);
}

__global__ void __launch_bounds__(256, 2) k_pv() {
    int z = blockIdx.z;
    int b = z >> 5, h = z & 31, kvh = h >> 2;
    const half_t* A = g_P + (size_t)z * SEQ * SEQ;
    const half_t* B = g_Vt + ((size_t)b * KVD + kvh * HD) * SEQ;
    float* C = g_Af + (size_t)b * SEQ * DIM + h * HD;
    gemm_hf(A, SEQ, B, SEQ, C, DIM, SEQ, blockIdx.y * 128, 0);
}

// ---------------- converts ----------------
__global__ void k_conv(const float2* __restrict__ in, __half2* __restrict__ out, int n2) {
    for (int i = blockIdx.x * 256 + threadIdx.x; i < n2; i += gridDim.x * 256) {
        float2 v = in[i];
        out[i] = __floats2half2_rn(v.x, v.y);
    }
}

// out[z][c, r] = (half)in[z][r, c]
__global__ void k_tconv(const float* __restrict__ in, size_t in_bs, int ld_in,
                        half_t* __restrict__ out, size_t out_bs, int ld_out)
{
    __shared__ float tile[32][33];
    const float* inp = in + blockIdx.z * in_bs;
    int r0 = blockIdx.y * 32, c0 = blockIdx.x * 32;
    for (int i = threadIdx.y; i < 32; i += 8)
        tile[i][threadIdx.x] = inp[(size_t)(r0 + i) * ld_in + c0 + threadIdx.x];
    __syncthreads();
    half_t* op = out + blockIdx.z * out_bs;
    for (int i = threadIdx.y; i < 32; i += 8)
        op[(size_t)(c0 + i) * ld_out + r0 + threadIdx.x] = __float2half(tile[threadIdx.x][i]);
}

// ---------------- RoPE: fp32 in -> fp16 out ----------------
__global__ void k_rope(const float* __restrict__ in, half_t* __restrict__ out,
                       const float* __restrict__ cs, const float* __restrict__ sn, int nh)
{
    int idx = blockIdx.x * 256 + threadIdx.x;
    int i = idx & 63, th = idx >> 6;
    int s = (th / nh) & (SEQ - 1);
    float c = cs[s * 64 + i], si = sn[s * 64 + i];
    size_t off = (size_t)th * HD + 2 * i;
    float v0 = in[off], v1 = in[off + 1];
    out[off]     = __float2half(v0 * c - v1 * si);
    out[off + 1] = __float2half(v0 * si + v1 * c);
}

// ---------------- softmax: fp32 scores -> fp16 probs ----------------
__global__ void k_softmax() {
    size_t row = blockIdx.x;
    const float* p = g_S + row * SEQ;
    half_t* po = g_P + row * SEQ;
    int tid = threadIdx.x;
    int lane = tid & 31, warp = tid >> 5;

    float v[8];
    float m = -1e30f;
#pragma unroll
    for (int i = 0; i < 8; i++) { v[i] = p[tid + i * 128] * SCALE; m = fmaxf(m, v[i]); }
#pragma unroll
    for (int o = 16; o; o >>= 1) m = fmaxf(m, __shfl_xor_sync(0xffffffffu, m, o));
    __shared__ float sm[4];
    if (!lane) sm[warp] = m;
    __syncthreads();
    m = fmaxf(fmaxf(sm[0], sm[1]), fmaxf(sm[2], sm[3]));

    float sum = 0.0f;
#pragma unroll
    for (int i = 0; i < 8; i++) { v[i] = __expf(v[i] - m); sum += v[i]; }
#pragma unroll
    for (int o = 16; o; o >>= 1) sum += __shfl_xor_sync(0xffffffffu, sum, o);
    __shared__ float ss[4];
    if (!lane) ss[warp] = sum;
    __syncthreads();
    sum = ss[0] + ss[1] + ss[2] + ss[3];

    float inv = 1.0f / sum;
#pragma unroll
    for (int i = 0; i < 8; i++) po[tid + i * 128] = __float2half(v[i] * inv);
}

// ---------------- launch ----------------
extern "C" void kernel_launch(void* const* d_in, const int* in_sizes, int n_in,
                              void* d_out, int out_size)
{
    const float* x  = (const float*)d_in[0];
    const float* fc = (const float*)d_in[1];
    const float* fs = (const float*)d_in[2];
    const float* wq = (const float*)d_in[3];
    const float* wk = (const float*)d_in[4];
    const float* wv = (const float*)d_in[5];
    const float* wo = (const float*)d_in[6];
    float* out = (float*)d_out;

    cudaFuncSetAttribute(k_proj,  cudaFuncAttributeMaxDynamicSharedMemorySize, SMEM_HF);
    cudaFuncSetAttribute(k_score, cudaFuncAttributeMaxDynamicSharedMemorySize, SMEM_HF);
    cudaFuncSetAttribute(k_pv,    cudaFuncAttributeMaxDynamicSharedMemorySize, SMEM_HF);

    half_t *xh, *wqt, *wkt, *wvt, *wot, *Qh, *Kh, *Vt, *Ah;
    float *Qf, *Kf, *Vf, *Af;
    cudaGetSymbolAddress((void**)&xh,  g_xh);
    cudaGetSymbolAddress((void**)&wqt, g_wqt);
    cudaGetSymbolAddress((void**)&wkt, g_wkt);
    cudaGetSymbolAddress((void**)&wvt, g_wvt);
    cudaGetSymbolAddress((void**)&wot, g_wot);
    cudaGetSymbolAddress((void**)&Qf,  g_Qf);
    cudaGetSymbolAddress((void**)&Kf,  g_Kf);
    cudaGetSymbolAddress((void**)&Vf,  g_Vf);
    cudaGetSymbolAddress((void**)&Qh,  g_Qh);
    cudaGetSymbolAddress((void**)&Kh,  g_Kh);
    cudaGetSymbolAddress((void**)&Vt,  g_Vt);
    cudaGetSymbolAddress((void**)&Af,  g_Af);
    cudaGetSymbolAddress((void**)&Ah,  g_Ah);

    dim3 tb(32, 8);

    // 1) convert x; transpose+convert weights to [N,K] fp16
    k_conv<<<4096, 256>>>((const float2*)x, (__half2*)xh, NTOK * DIM / 2);
    k_tconv<<<dim3(DIM / 32, DIM / 32, 1), tb>>>(wq, 0, DIM, wqt, 0, DIM);
    k_tconv<<<dim3(KVD / 32, DIM / 32, 1), tb>>>(wk, 0, KVD, wkt, 0, DIM);
    k_tconv<<<dim3(KVD / 32, DIM / 32, 1), tb>>>(wv, 0, KVD, wvt, 0, DIM);
    k_tconv<<<dim3(DIM / 32, DIM / 32, 1), tb>>>(wo, 0, DIM, wot, 0, DIM);

    // 2) QKV projections
    k_proj<<<dim3(DIM / 128, NTOK / 128), 256, SMEM_HF>>>(xh, wqt, Qf, DIM, DIM, DIM, DIM);
    k_proj<<<dim3(KVD / 128, NTOK / 128), 256, SMEM_HF>>>(xh, wkt, Kf, DIM, DIM, KVD, DIM);
    k_proj<<<dim3(KVD / 128, NTOK / 128), 256, SMEM_HF>>>(xh, wvt, Vf, DIM, DIM, KVD, DIM);

    // 3) RoPE -> fp16; V transpose -> [kv*d, s] fp16
    k_rope<<<(NTOK * NH * 64) / 256, 256>>>(Qf, Qh, fc, fs, NH);
    k_rope<<<(NTOK * NKV * 64) / 256, 256>>>(Kf, Kh, fc, fs, NKV);
    k_tconv<<<dim3(KVD / 32, SEQ / 32, BATCH), tb>>>(Vf, (size_t)SEQ * KVD, KVD,
                                                     Vt, (size_t)KVD * SEQ, SEQ);

    // 4) attention
    k_score<<<dim3(SEQ / 128, SEQ / 128, BATCH * NH), 256, SMEM_HF>>>();
    k_softmax<<<BATCH * NH * SEQ, 128>>>();
    k_pv<<<dim3(1, SEQ / 128, BATCH * NH), 256, SMEM_HF>>>();

    // 5) output projection
    k_conv<<<4096, 256>>>((const float2*)Af, (__half2*)Ah, NTOK * DIM / 2);
    k_proj<<<dim3(DIM / 128, DIM / 128), 256, SMEM_HF>>>(Ah, wot, out, DIM, DIM, DIM, DIM);
}

// round 12
// speedup vs baseline: 3.7843x; 1.1189x over previous
#include <cuda_runtime.h>
#include <cuda_fp16.h>
#include <cuda_pipeline.h>
#include <mma.h>
#include <math.h>
#include <stdint.h>

using namespace nvcuda;

#define BATCH 4
#define SEQ   1024
#define DIM   4096
#define NH    32
#define NKV   8
#define HD    128
#define KVD   (NKV*HD)            // 1024
#define NTOK  (BATCH*SEQ)         // 4096
#define SCALE 0.08838834764831845f

#define BK   64                   // halves per k-chunk in proj GEMM
#define STR  72                   // proj smem stride (halves)
#define FSTR 136                  // flash smem stride (halves), 272B rows

typedef __half half_t;

// ---------------- scratch (device globals) ----------------
__device__ half_t g_xh [(size_t)NTOK * DIM];
__device__ half_t g_wqt[(size_t)DIM * DIM];     // [N,K] transposed
__device__ half_t g_wkt[(size_t)KVD * DIM];
__device__ half_t g_wvt[(size_t)KVD * DIM];
__device__ half_t g_wot[(size_t)DIM * DIM];
__device__ float  g_Qf [(size_t)NTOK * DIM];
__device__ float  g_Kf [(size_t)NTOK * KVD];
__device__ float  g_Vf [(size_t)NTOK * KVD];
__device__ half_t g_Qh [(size_t)NTOK * DIM];
__device__ half_t g_Kh [(size_t)NTOK * KVD];
__device__ half_t g_Vh [(size_t)NTOK * KVD];
__device__ half_t g_Ah [(size_t)NTOK * DIM];

// ---------------- fp16 wmma GEMM (unchanged engine from R10) ----------------
__device__ __forceinline__ void gemm_hf(const half_t* __restrict__ A, int lda,
                                        const half_t* __restrict__ B, int ldb,
                                        float* __restrict__ C, int ldc, int K,
                                        int bm, int bn)
{
    extern __shared__ half_t sm[];
    half_t* sA[2] = { sm,                 sm + 128 * STR };
    half_t* sB[2] = { sm + 2 * 128 * STR, sm + 3 * 128 * STR };

    const int tid  = threadIdx.x;
    const int warp = tid >> 5;
    const int wm   = (warp >> 1) * 32;
    const int wn   = (warp & 1) * 64;

    wmma::fragment<wmma::accumulator, 16, 16, 16, float> acc[2][4];
#pragma unroll
    for (int i = 0; i < 2; i++)
#pragma unroll
        for (int j = 0; j < 4; j++) wmma::fill_fragment(acc[i][j], 0.0f);

    auto load_tile = [&](int st, int k0) {
#pragma unroll
        for (int l = 0; l < 4; l++) {
            int idx = l * 256 + tid;
            int r = idx >> 3, c8 = idx & 7;
            __pipeline_memcpy_async(&sA[st][r * STR + c8 * 8],
                                    &A[(size_t)(bm + r) * lda + k0 + c8 * 8], 16);
            __pipeline_memcpy_async(&sB[st][r * STR + c8 * 8],
                                    &B[(size_t)(bn + r) * ldb + k0 + c8 * 8], 16);
        }
    };

    const int nt = K / BK;
    load_tile(0, 0);
    __pipeline_commit();

    for (int t = 0; t < nt; t++) {
        if (t + 1 < nt) {
            load_tile((t + 1) & 1, (t + 1) * BK);
            __pipeline_commit();
            __pipeline_wait_prior(1);
        } else {
            __pipeline_wait_prior(0);
        }
        __syncthreads();

        const int st = t & 1;
#pragma unroll
        for (int kk = 0; kk < BK; kk += 16) {
            wmma::fragment<wmma::matrix_a, 16, 16, 16, half_t, wmma::row_major> af[2];
#pragma unroll
            for (int i = 0; i < 2; i++)
                wmma::load_matrix_sync(af[i], &sA[st][(wm + i * 16) * STR + kk], STR);
            wmma::fragment<wmma::matrix_b, 16, 16, 16, half_t, wmma::col_major> bf[4];
#pragma unroll
            for (int j = 0; j < 4; j++)
                wmma::load_matrix_sync(bf[j], &sB[st][(wn + j * 16) * STR + kk], STR);
#pragma unroll
            for (int i = 0; i < 2; i++)
#pragma unroll
                for (int j = 0; j < 4; j++)
                    wmma::mma_sync(acc[i][j], af[i], bf[j], acc[i][j]);
        }
        __syncthreads();
    }

#pragma unroll
    for (int i = 0; i < 2; i++)
#pragma unroll
        for (int j = 0; j < 4; j++)
            wmma::store_matrix_sync(&C[(size_t)(bm + wm + i * 16) * ldc + bn + wn + j * 16],
                                    acc[i][j], ldc, wmma::mem_row_major);
}

#define SMEM_HF (4 * 128 * STR * (int)sizeof(half_t))     // 73728 B
#define SMEM_FL (5 * 128 * FSTR * (int)sizeof(half_t))    // 174080 B

__global__ void __launch_bounds__(256, 2) k_proj(const half_t* A, const half_t* B,
                                                 float* C, int lda, int ldb, int ldc, int K)
{
    gemm_hf(A, lda, B, ldb, C, ldc, K, blockIdx.y * 128, blockIdx.x * 128);
}

// ---------------- mma.sync helpers ----------------
__device__ __forceinline__ void ldsm4(uint32_t* r, const half_t* p) {
    uint32_t a = (uint32_t)__cvta_generic_to_shared(p);
    asm volatile("ldmatrix.sync.aligned.m8n8.x4.shared.b16 {%0,%1,%2,%3}, [%4];"
        : "=r"(r[0]), "=r"(r[1]), "=r"(r[2]), "=r"(r[3]) : "r"(a));
}
__device__ __forceinline__ void ldsm4t(uint32_t* r, const half_t* p) {
    uint32_t a = (uint32_t)__cvta_generic_to_shared(p);
    asm volatile("ldmatrix.sync.aligned.m8n8.x4.trans.shared.b16 {%0,%1,%2,%3}, [%4];"
        : "=r"(r[0]), "=r"(r[1]), "=r"(r[2]), "=r"(r[3]) : "r"(a));
}
__device__ __forceinline__ void mma16816(float* c, const uint32_t* a, uint32_t b0, uint32_t b1) {
    asm volatile("mma.sync.aligned.m16n8k16.row.col.f32.f16.f16.f32 "
        "{%0,%1,%2,%3}, {%4,%5,%6,%7}, {%8,%9}, {%0,%1,%2,%3};"
        : "+f"(c[0]), "+f"(c[1]), "+f"(c[2]), "+f"(c[3])
        : "r"(a[0]), "r"(a[1]), "r"(a[2]), "r"(a[3]), "r"(b0), "r"(b1));
}
__device__ __forceinline__ uint32_t packh2(float a, float b) {
    __half2 h = __floats2half2_rn(a, b);
    return *(uint32_t*)&h;
}

// ---------------- fused flash attention ----------------
// grid (SEQ/128, BATCH*NH), 256 threads. Q tile resident; K/V 128-key tiles
// double-buffered. Warp w owns q-rows w*16..w*16+15.
__global__ void __launch_bounds__(256, 1) k_flash() {
    int z = blockIdx.y, b = z >> 5, h = z & 31, kvh = h >> 2;
    int q0 = blockIdx.x * 128;
    const half_t* Qp = g_Qh + ((size_t)b * SEQ + q0) * DIM + h * HD;
    const half_t* Kp = g_Kh + (size_t)b * SEQ * KVD + kvh * HD;
    const half_t* Vp = g_Vh + (size_t)b * SEQ * KVD + kvh * HD;
    half_t*       Op = g_Ah + ((size_t)b * SEQ + q0) * DIM + h * HD;

    extern __shared__ half_t sm[];
    half_t* sQ = sm;                    // 128 x FSTR
    half_t* sK = sm + 128 * FSTR;       // 2 stages
    half_t* sV = sm + 3 * 128 * FSTR;   // 2 stages

    const int tid = threadIdx.x, warp = tid >> 5, lane = tid & 31;
    const int q0w = warp * 16;

    // Q tile: 128 rows x 128 halves (16 uint4/row)
    for (int i = tid; i < 128 * 16; i += 256) {
        int r = i >> 4, c = i & 15;
        *(uint4*)&sQ[r * FSTR + c * 8] = *(const uint4*)&Qp[(size_t)r * DIM + c * 8];
    }

    auto loadKV = [&](int st, int t) {
        const half_t* kp = Kp + (size_t)t * 128 * KVD;
        const half_t* vp = Vp + (size_t)t * 128 * KVD;
        half_t* dk = sK + st * 128 * FSTR;
        half_t* dv = sV + st * 128 * FSTR;
#pragma unroll
        for (int l = 0; l < 8; l++) {
            int i = l * 256 + tid;              // 2048 chunks of 16B each
            int r = i >> 4, c = i & 15;
            __pipeline_memcpy_async(&dk[r * FSTR + c * 8], &kp[(size_t)r * KVD + c * 8], 16);
            __pipeline_memcpy_async(&dv[r * FSTR + c * 8], &vp[(size_t)r * KVD + c * 8], 16);
        }
    };

    loadKV(0, 0);
    __pipeline_commit();
    __syncthreads();   // Q visible before mainloop ldmatrix

    float oacc[16][4];
#pragma unroll
    for (int j = 0; j < 16; j++)
#pragma unroll
        for (int e = 0; e < 4; e++) oacc[j][e] = 0.0f;
    float mr0 = -1e30f, mr1 = -1e30f, lr0 = 0.0f, lr1 = 0.0f;

    for (int t = 0; t < SEQ / 128; t++) {
        if (t + 1 < SEQ / 128) {
            loadKV((t + 1) & 1, t + 1);
            __pipeline_commit();
            __pipeline_wait_prior(1);
        } else {
            __pipeline_wait_prior(0);
        }
        __syncthreads();
        const half_t* kst = sK + (t & 1) * 128 * FSTR;
        const half_t* vst = sV + (t & 1) * 128 * FSTR;

        // ---- S = Q K^T (16 q-rows x 128 keys per warp) ----
        float sacc[16][4];
#pragma unroll
        for (int j = 0; j < 16; j++)
#pragma unroll
            for (int e = 0; e < 4; e++) sacc[j][e] = 0.0f;

#pragma unroll
        for (int kd = 0; kd < 8; kd++) {
            uint32_t a[4];
            ldsm4(a, &sQ[(q0w + (lane & 15)) * FSTR + kd * 16 + (lane >> 4) * 8]);
#pragma unroll
            for (int nb = 0; nb < 8; nb++) {
                uint32_t bb[4];
                int key = nb * 16 + (lane & 7) + ((lane >> 4) << 3);
                int dc  = kd * 16 + (((lane >> 3) & 1) << 3);
                ldsm4(bb, &kst[key * FSTR + dc]);
                mma16816(sacc[2 * nb],     a, bb[0], bb[1]);
                mma16816(sacc[2 * nb + 1], a, bb[2], bb[3]);
            }
        }

        // ---- online softmax ----
        float tm0 = -1e30f, tm1 = -1e30f;
#pragma unroll
        for (int j = 0; j < 16; j++) {
            sacc[j][0] *= SCALE; sacc[j][1] *= SCALE;
            sacc[j][2] *= SCALE; sacc[j][3] *= SCALE;
            tm0 = fmaxf(tm0, fmaxf(sacc[j][0], sacc[j][1]));
            tm1 = fmaxf(tm1, fmaxf(sacc[j][2], sacc[j][3]));
        }
        tm0 = fmaxf(tm0, __shfl_xor_sync(0xffffffffu, tm0, 1));
        tm0 = fmaxf(tm0, __shfl_xor_sync(0xffffffffu, tm0, 2));
        tm1 = fmaxf(tm1, __shfl_xor_sync(0xffffffffu, tm1, 1));
        tm1 = fmaxf(tm1, __shfl_xor_sync(0xffffffffu, tm1, 2));
        float mn0 = fmaxf(mr0, tm0), mn1 = fmaxf(mr1, tm1);
        float cor0 = __expf(mr0 - mn0), cor1 = __expf(mr1 - mn1);
        mr0 = mn0; mr1 = mn1;

        uint32_t ph[16][2];
        float rs0 = 0.0f, rs1 = 0.0f;
#pragma unroll
        for (int j = 0; j < 16; j++) {
            float e0 = __expf(sacc[j][0] - mn0), e1 = __expf(sacc[j][1] - mn0);
            float e2 = __expf(sacc[j][2] - mn1), e3 = __expf(sacc[j][3] - mn1);
            rs0 += e0 + e1; rs1 += e2 + e3;
            ph[j][0] = packh2(e0, e1);
            ph[j][1] = packh2(e2, e3);
        }
        rs0 += __shfl_xor_sync(0xffffffffu, rs0, 1);
        rs0 += __shfl_xor_sync(0xffffffffu, rs0, 2);
        rs1 += __shfl_xor_sync(0xffffffffu, rs1, 1);
        rs1 += __shfl_xor_sync(0xffffffffu, rs1, 2);
        lr0 = lr0 * cor0 + rs0;
        lr1 = lr1 * cor1 + rs1;
#pragma unroll
        for (int j = 0; j < 16; j++) {
            oacc[j][0] *= cor0; oacc[j][1] *= cor0;
            oacc[j][2] *= cor1; oacc[j][3] *= cor1;
        }

        // ---- O += P V ----
#pragma unroll
        for (int kk = 0; kk < 8; kk++) {
            uint32_t pa[4] = { ph[2 * kk][0], ph[2 * kk][1], ph[2 * kk + 1][0], ph[2 * kk + 1][1] };
#pragma unroll
            for (int nb = 0; nb < 8; nb++) {
                uint32_t bb[4];
                int key = kk * 16 + (lane & 7) + (((lane >> 3) & 1) << 3);
                int dc  = nb * 16 + ((lane >> 4) << 3);
                ldsm4t(bb, &vst[key * FSTR + dc]);
                mma16816(oacc[2 * nb],     pa, bb[0], bb[1]);
                mma16816(oacc[2 * nb + 1], pa, bb[2], bb[3]);
            }
        }
        __syncthreads();   // stage consumed; safe to overwrite next iter
    }

    // ---- epilogue: normalize, write fp16 ----
    float il0 = 1.0f / lr0, il1 = 1.0f / lr1;
    int r0 = q0w + (lane >> 2), c0 = (lane & 3) * 2;
#pragma unroll
    for (int j = 0; j < 16; j++) {
        __half2 h0 = __floats2half2_rn(oacc[j][0] * il0, oacc[j][1] * il0);
        __half2 h1 = __floats2half2_rn(oacc[j][2] * il1, oacc[j][3] * il1);
        *(__half2*)&Op[(size_t)r0 * DIM + j * 8 + c0] = h0;
        *(__half2*)&Op[(size_t)(r0 + 8) * DIM + j * 8 + c0] = h1;
    }
}

// ---------------- converts ----------------
__global__ void k_conv(const float2* __restrict__ in, __half2* __restrict__ out, int n2) {
    for (int i = blockIdx.x * 256 + threadIdx.x; i < n2; i += gridDim.x * 256) {
        float2 v = in[i];
        out[i] = __floats2half2_rn(v.x, v.y);
    }
}

__global__ void k_tconv(const float* __restrict__ in, size_t in_bs, int ld_in,
                        half_t* __restrict__ out, size_t out_bs, int ld_out)
{
    __shared__ float tile[32][33];
    const float* inp = in + blockIdx.z * in_bs;
    int r0 = blockIdx.y * 32, c0 = blockIdx.x * 32;
    for (int i = threadIdx.y; i < 32; i += 8)
        tile[i][threadIdx.x] = inp[(size_t)(r0 + i) * ld_in + c0 + threadIdx.x];
    __syncthreads();
    half_t* op = out + blockIdx.z * out_bs;
    for (int i = threadIdx.y; i < 32; i += 8)
        op[(size_t)(c0 + i) * ld_out + r0 + threadIdx.x] = __float2half(tile[threadIdx.x][i]);
}

// ---------------- RoPE: fp32 in -> fp16 out ----------------
__global__ void k_rope(const float* __restrict__ in, half_t* __restrict__ out,
                       const float* __restrict__ cs, const float* __restrict__ sn, int nh)
{
    int idx = blockIdx.x * 256 + threadIdx.x;
    int i = idx & 63, th = idx >> 6;
    int s = (th / nh) & (SEQ - 1);
    float c = cs[s * 64 + i], si = sn[s * 64 + i];
    size_t off = (size_t)th * HD + 2 * i;
    float v0 = in[off], v1 = in[off + 1];
    out[off]     = __float2half(v0 * c - v1 * si);
    out[off + 1] = __float2half(v0 * si + v1 * c);
}

// ---------------- launch ----------------
extern "C" void kernel_launch(void* const* d_in, const int* in_sizes, int n_in,
                              void* d_out, int out_size)
{
    const float* x  = (const float*)d_in[0];
    const float* fc = (const float*)d_in[1];
    const float* fs = (const float*)d_in[2];
    const float* wq = (const float*)d_in[3];
    const float* wk = (const float*)d_in[4];
    const float* wv = (const float*)d_in[5];
    const float* wo = (const float*)d_in[6];
    float* out = (float*)d_out;

    cudaFuncSetAttribute(k_proj,  cudaFuncAttributeMaxDynamicSharedMemorySize, SMEM_HF);
    cudaFuncSetAttribute(k_flash, cudaFuncAttributeMaxDynamicSharedMemorySize, SMEM_FL);

    half_t *xh, *wqt, *wkt, *wvt, *wot, *Qh, *Kh, *Vh, *Ah;
    float *Qf, *Kf, *Vf;
    cudaGetSymbolAddress((void**)&xh,  g_xh);
    cudaGetSymbolAddress((void**)&wqt, g_wqt);
    cudaGetSymbolAddress((void**)&wkt, g_wkt);
    cudaGetSymbolAddress((void**)&wvt, g_wvt);
    cudaGetSymbolAddress((void**)&wot, g_wot);
    cudaGetSymbolAddress((void**)&Qf,  g_Qf);
    cudaGetSymbolAddress((void**)&Kf,  g_Kf);
    cudaGetSymbolAddress((void**)&Vf,  g_Vf);
    cudaGetSymbolAddress((void**)&Qh,  g_Qh);
    cudaGetSymbolAddress((void**)&Kh,  g_Kh);
    cudaGetSymbolAddress((void**)&Vh,  g_Vh);
    cudaGetSymbolAddress((void**)&Ah,  g_Ah);

    dim3 tb(32, 8);

    // 1) convert x; transpose+convert weights
    k_conv<<<4096, 256>>>((const float2*)x, (__half2*)xh, NTOK * DIM / 2);
    k_tconv<<<dim3(DIM / 32, DIM / 32, 1), tb>>>(wq, 0, DIM, wqt, 0, DIM);
    k_tconv<<<dim3(KVD / 32, DIM / 32, 1), tb>>>(wk, 0, KVD, wkt, 0, DIM);
    k_tconv<<<dim3(KVD / 32, DIM / 32, 1), tb>>>(wv, 0, KVD, wvt, 0, DIM);
    k_tconv<<<dim3(DIM / 32, DIM / 32, 1), tb>>>(wo, 0, DIM, wot, 0, DIM);

    // 2) QKV projections
    k_proj<<<dim3(DIM / 128, NTOK / 128), 256, SMEM_HF>>>(xh, wqt, Qf, DIM, DIM, DIM, DIM);
    k_proj<<<dim3(KVD / 128, NTOK / 128), 256, SMEM_HF>>>(xh, wkt, Kf, DIM, DIM, KVD, DIM);
    k_proj<<<dim3(KVD / 128, NTOK / 128), 256, SMEM_HF>>>(xh, wvt, Vf, DIM, DIM, KVD, DIM);

    // 3) RoPE -> fp16; V -> fp16 (natural [token][kvd] layout)
    k_rope<<<(NTOK * NH * 64) / 256, 256>>>(Qf, Qh, fc, fs, NH);
    k_rope<<<(NTOK * NKV * 64) / 256, 256>>>(Kf, Kh, fc, fs, NKV);
    k_conv<<<2048, 256>>>((const float2*)Vf, (__half2*)Vh, NTOK * KVD / 2);

    // 4) fused attention (scores + softmax + PV), fp16 out
    k_flash<<<dim3(SEQ / 128, BATCH * NH), 256, SMEM_FL>>>();

    // 5) output projection
    k_proj<<<dim3(DIM / 128, DIM / 128), 256, SMEM_HF>>>(Ah, wot, out, DIM, DIM, DIM, DIM);
}

// round 13
// speedup vs baseline: 4.5564x; 1.2040x over previous
#include <cuda_runtime.h>
#include <cuda_fp16.h>
#include <cuda_pipeline.h>
#include <math.h>
#include <stdint.h>

#define BATCH 4
#define SEQ   1024
#define DIM   4096
#define NH    32
#define NKV   8
#define HD    128
#define KVD   (NKV*HD)            // 1024
#define NTOK  (BATCH*SEQ)         // 4096
#define SCALE 0.08838834764831845f

#define STR  72                   // A smem stride (halves)
#define BSTR 136                  // B smem stride (halves)
#define FSTR 136                  // flash smem stride (halves)

typedef __half half_t;

// ---------------- scratch (device globals) ----------------
__device__ half_t g_xh [(size_t)NTOK * DIM];
__device__ half_t g_wqh[(size_t)DIM * DIM];     // natural [K,N] fp16
__device__ half_t g_wkh[(size_t)DIM * KVD];
__device__ half_t g_wvh[(size_t)DIM * KVD];
__device__ half_t g_woh[(size_t)DIM * DIM];
__device__ half_t g_Qh [(size_t)NTOK * DIM];
__device__ half_t g_Kh [(size_t)NTOK * KVD];
__device__ half_t g_Vh [(size_t)NTOK * KVD];
__device__ half_t g_Ah [(size_t)NTOK * DIM];

// ---------------- mma.sync helpers ----------------
__device__ __forceinline__ void ldsm4(uint32_t* r, const half_t* p) {
    uint32_t a = (uint32_t)__cvta_generic_to_shared(p);
    asm volatile("ldmatrix.sync.aligned.m8n8.x4.shared.b16 {%0,%1,%2,%3}, [%4];"
        : "=r"(r[0]), "=r"(r[1]), "=r"(r[2]), "=r"(r[3]) : "r"(a));
}
__device__ __forceinline__ void ldsm4t(uint32_t* r, const half_t* p) {
    uint32_t a = (uint32_t)__cvta_generic_to_shared(p);
    asm volatile("ldmatrix.sync.aligned.m8n8.x4.trans.shared.b16 {%0,%1,%2,%3}, [%4];"
        : "=r"(r[0]), "=r"(r[1]), "=r"(r[2]), "=r"(r[3]) : "r"(a));
}
__device__ __forceinline__ void mma16816(float* c, const uint32_t* a, uint32_t b0, uint32_t b1) {
    asm volatile("mma.sync.aligned.m16n8k16.row.col.f32.f16.f16.f32 "
        "{%0,%1,%2,%3}, {%4,%5,%6,%7}, {%8,%9}, {%0,%1,%2,%3};"
        : "+f"(c[0]), "+f"(c[1]), "+f"(c[2]), "+f"(c[3])
        : "r"(a[0]), "r"(a[1]), "r"(a[2]), "r"(a[3]), "r"(b0), "r"(b1));
}
__device__ __forceinline__ uint32_t packh2(float a, float b) {
    __half2 h = __floats2half2_rn(a, b);
    return *(uint32_t*)&h;
}

// ---------------- projection GEMM: C[M,N] = A[M,K] @ B[K,N] -------------------
// A row-major fp16, B row-major fp16 (natural), fp32 accum.
// 256 threads = 8 warps (4m x 2n); warp tile 32x64 = 2x8 mma m16n8k16.
// cp.async double-buffered, BK=64. EPI: 0 = fp32 store, 1 = fp16 store,
// 2 = fp16 store with fused RoPE (cols form (even,odd) head-dim pairs).
template<int EPI>
__device__ __forceinline__ void gemm_proj(const half_t* __restrict__ A, int lda,
                                          const half_t* __restrict__ B, int ldb,
                                          void* __restrict__ Cv, int ldc, int K,
                                          int bm, int bn,
                                          const float* __restrict__ cs,
                                          const float* __restrict__ sn)
{
    extern __shared__ half_t sm[];
    half_t* sA[2] = { sm,              sm + 128 * STR };
    half_t* sB[2] = { sm + 2 * 128 * STR, sm + 2 * 128 * STR + 64 * BSTR };

    const int tid = threadIdx.x, warp = tid >> 5, lane = tid & 31;
    const int wm = (warp >> 1) * 32;
    const int wn = (warp & 1) * 64;

    float acc[2][8][4];
#pragma unroll
    for (int mi = 0; mi < 2; mi++)
#pragma unroll
        for (int nb = 0; nb < 8; nb++)
#pragma unroll
            for (int e = 0; e < 4; e++) acc[mi][nb][e] = 0.0f;

    auto load_tile = [&](int st, int k0) {
        // A: 128 rows x 64 halves = 1024 chunks of 16B
#pragma unroll
        for (int l = 0; l < 4; l++) {
            int idx = l * 256 + tid;
            int r = idx >> 3, c8 = idx & 7;
            __pipeline_memcpy_async(&sA[st][r * STR + c8 * 8],
                                    &A[(size_t)(bm + r) * lda + k0 + c8 * 8], 16);
        }
        // B: 64 rows x 128 halves = 1024 chunks of 16B
#pragma unroll
        for (int l = 0; l < 4; l++) {
            int idx = l * 256 + tid;
            int r = idx >> 4, c8 = idx & 15;
            __pipeline_memcpy_async(&sB[st][r * BSTR + c8 * 8],
                                    &B[(size_t)(k0 + r) * ldb + bn + c8 * 8], 16);
        }
    };

    const int nt = K / 64;
    load_tile(0, 0);
    __pipeline_commit();

    for (int t = 0; t < nt; t++) {
        if (t + 1 < nt) {
            load_tile((t + 1) & 1, (t + 1) * 64);
            __pipeline_commit();
            __pipeline_wait_prior(1);
        } else {
            __pipeline_wait_prior(0);
        }
        __syncthreads();

        const int st = t & 1;
#pragma unroll
        for (int kk = 0; kk < 64; kk += 16) {
            uint32_t a0[4], a1[4];
            ldsm4(a0, &sA[st][(wm + (lane & 15)) * STR + kk + (lane >> 4) * 8]);
            ldsm4(a1, &sA[st][(wm + 16 + (lane & 15)) * STR + kk + (lane >> 4) * 8]);
#pragma unroll
            for (int nb2 = 0; nb2 < 4; nb2++) {
                uint32_t bb[4];
                int kr = kk + (lane & 7) + (((lane >> 3) & 1) << 3);
                int nc = wn + nb2 * 16 + ((lane >> 4) << 3);
                ldsm4t(bb, &sB[st][kr * BSTR + nc]);
                mma16816(acc[0][2 * nb2],     a0, bb[0], bb[1]);
                mma16816(acc[0][2 * nb2 + 1], a0, bb[2], bb[3]);
                mma16816(acc[1][2 * nb2],     a1, bb[0], bb[1]);
                mma16816(acc[1][2 * nb2 + 1], a1, bb[2], bb[3]);
            }
        }
        __syncthreads();
    }

    // ---- epilogue ----
#pragma unroll
    for (int mi = 0; mi < 2; mi++) {
        int r0 = bm + wm + mi * 16 + (lane >> 2);
#pragma unroll
        for (int nb = 0; nb < 8; nb++) {
            int c = bn + wn + nb * 8 + (lane & 3) * 2;
            float v0 = acc[mi][nb][0], v1 = acc[mi][nb][1];
            float v2 = acc[mi][nb][2], v3 = acc[mi][nb][3];
            if (EPI == 0) {
                float* C = (float*)Cv;
                *(float2*)&C[(size_t)r0 * ldc + c]       = make_float2(v0, v1);
                *(float2*)&C[(size_t)(r0 + 8) * ldc + c] = make_float2(v2, v3);
            } else if (EPI == 1) {
                half_t* C = (half_t*)Cv;
                *(__half2*)&C[(size_t)r0 * ldc + c]       = __floats2half2_rn(v0, v1);
                *(__half2*)&C[(size_t)(r0 + 8) * ldc + c] = __floats2half2_rn(v2, v3);
            } else {
                half_t* C = (half_t*)Cv;
                int i = (c & 127) >> 1;
                int s0 = r0 & (SEQ - 1), s1 = (r0 + 8) & (SEQ - 1);
                float c0 = cs[s0 * 64 + i], z0 = sn[s0 * 64 + i];
                float c1 = cs[s1 * 64 + i], z1 = sn[s1 * 64 + i];
                *(__half2*)&C[(size_t)r0 * ldc + c] =
                    __floats2half2_rn(v0 * c0 - v1 * z0, v0 * z0 + v1 * c0);
                *(__half2*)&C[(size_t)(r0 + 8) * ldc + c] =
                    __floats2half2_rn(v2 * c1 - v3 * z1, v2 * z1 + v3 * c1);
            }
        }
    }
}

#define SMEM_PJ ((2 * 128 * STR + 2 * 64 * BSTR) * (int)sizeof(half_t))  // 71680 B
#define SMEM_FL (5 * 128 * FSTR * (int)sizeof(half_t))                   // 174080 B

__global__ void __launch_bounds__(256, 2) k_proj_rope(const half_t* A, const half_t* B,
                                                      half_t* C, int ldb, int ldc, int K,
                                                      const float* cs, const float* sn)
{
    gemm_proj<2>(A, DIM, B, ldb, C, ldc, K, blockIdx.y * 128, blockIdx.x * 128, cs, sn);
}
__global__ void __launch_bounds__(256, 2) k_proj_h(const half_t* A, const half_t* B,
                                                   half_t* C, int ldb, int ldc, int K)
{
    gemm_proj<1>(A, DIM, B, ldb, C, ldc, K, blockIdx.y * 128, blockIdx.x * 128, nullptr, nullptr);
}
__global__ void __launch_bounds__(256, 2) k_proj_f(const half_t* A, const half_t* B,
                                                   float* C, int ldb, int ldc, int K)
{
    gemm_proj<0>(A, DIM, B, ldb, C, ldc, K, blockIdx.y * 128, blockIdx.x * 128, nullptr, nullptr);
}

// ---------------- fused flash attention (unchanged from R12) ----------------
__global__ void __launch_bounds__(256, 1) k_flash() {
    int z = blockIdx.y, b = z >> 5, h = z & 31, kvh = h >> 2;
    int q0 = blockIdx.x * 128;
    const half_t* Qp = g_Qh + ((size_t)b * SEQ + q0) * DIM + h * HD;
    const half_t* Kp = g_Kh + (size_t)b * SEQ * KVD + kvh * HD;
    const half_t* Vp = g_Vh + (size_t)b * SEQ * KVD + kvh * HD;
    half_t*       Op = g_Ah + ((size_t)b * SEQ + q0) * DIM + h * HD;

    extern __shared__ half_t sm[];
    half_t* sQ = sm;
    half_t* sK = sm + 128 * FSTR;
    half_t* sV = sm + 3 * 128 * FSTR;

    const int tid = threadIdx.x, warp = tid >> 5, lane = tid & 31;
    const int q0w = warp * 16;

    for (int i = tid; i < 128 * 16; i += 256) {
        int r = i >> 4, c = i & 15;
        *(uint4*)&sQ[r * FSTR + c * 8] = *(const uint4*)&Qp[(size_t)r * DIM + c * 8];
    }

    auto loadKV = [&](int st, int t) {
        const half_t* kp = Kp + (size_t)t * 128 * KVD;
        const half_t* vp = Vp + (size_t)t * 128 * KVD;
        half_t* dk = sK + st * 128 * FSTR;
        half_t* dv = sV + st * 128 * FSTR;
#pragma unroll
        for (int l = 0; l < 8; l++) {
            int i = l * 256 + tid;
            int r = i >> 4, c = i & 15;
            __pipeline_memcpy_async(&dk[r * FSTR + c * 8], &kp[(size_t)r * KVD + c * 8], 16);
            __pipeline_memcpy_async(&dv[r * FSTR + c * 8], &vp[(size_t)r * KVD + c * 8], 16);
        }
    };

    loadKV(0, 0);
    __pipeline_commit();
    __syncthreads();

    float oacc[16][4];
#pragma unroll
    for (int j = 0; j < 16; j++)
#pragma unroll
        for (int e = 0; e < 4; e++) oacc[j][e] = 0.0f;
    float mr0 = -1e30f, mr1 = -1e30f, lr0 = 0.0f, lr1 = 0.0f;

    for (int t = 0; t < SEQ / 128; t++) {
        if (t + 1 < SEQ / 128) {
            loadKV((t + 1) & 1, t + 1);
            __pipeline_commit();
            __pipeline_wait_prior(1);
        } else {
            __pipeline_wait_prior(0);
        }
        __syncthreads();
        const half_t* kst = sK + (t & 1) * 128 * FSTR;
        const half_t* vst = sV + (t & 1) * 128 * FSTR;

        float sacc[16][4];
#pragma unroll
        for (int j = 0; j < 16; j++)
#pragma unroll
            for (int e = 0; e < 4; e++) sacc[j][e] = 0.0f;

#pragma unroll
        for (int kd = 0; kd < 8; kd++) {
            uint32_t a[4];
            ldsm4(a, &sQ[(q0w + (lane & 15)) * FSTR + kd * 16 + (lane >> 4) * 8]);
#pragma unroll
            for (int nb = 0; nb < 8; nb++) {
                uint32_t bb[4];
                int key = nb * 16 + (lane & 7) + ((lane >> 4) << 3);
                int dc  = kd * 16 + (((lane >> 3) & 1) << 3);
                ldsm4(bb, &kst[key * FSTR + dc]);
                mma16816(sacc[2 * nb],     a, bb[0], bb[1]);
                mma16816(sacc[2 * nb + 1], a, bb[2], bb[3]);
            }
        }

        float tm0 = -1e30f, tm1 = -1e30f;
#pragma unroll
        for (int j = 0; j < 16; j++) {
            sacc[j][0] *= SCALE; sacc[j][1] *= SCALE;
            sacc[j][2] *= SCALE; sacc[j][3] *= SCALE;
            tm0 = fmaxf(tm0, fmaxf(sacc[j][0], sacc[j][1]));
            tm1 = fmaxf(tm1, fmaxf(sacc[j][2], sacc[j][3]));
        }
        tm0 = fmaxf(tm0, __shfl_xor_sync(0xffffffffu, tm0, 1));
        tm0 = fmaxf(tm0, __shfl_xor_sync(0xffffffffu, tm0, 2));
        tm1 = fmaxf(tm1, __shfl_xor_sync(0xffffffffu, tm1, 1));
        tm1 = fmaxf(tm1, __shfl_xor_sync(0xffffffffu, tm1, 2));
        float mn0 = fmaxf(mr0, tm0), mn1 = fmaxf(mr1, tm1);
        float cor0 = __expf(mr0 - mn0), cor1 = __expf(mr1 - mn1);
        mr0 = mn0; mr1 = mn1;

        uint32_t ph[16][2];
        float rs0 = 0.0f, rs1 = 0.0f;
#pragma unroll
        for (int j = 0; j < 16; j++) {
            float e0 = __expf(sacc[j][0] - mn0), e1 = __expf(sacc[j][1] - mn0);
            float e2 = __expf(sacc[j][2] - mn1), e3 = __expf(sacc[j][3] - mn1);
            rs0 += e0 + e1; rs1 += e2 + e3;
            ph[j][0] = packh2(e0, e1);
            ph[j][1] = packh2(e2, e3);
        }
        rs0 += __shfl_xor_sync(0xffffffffu, rs0, 1);
        rs0 += __shfl_xor_sync(0xffffffffu, rs0, 2);
        rs1 += __shfl_xor_sync(0xffffffffu, rs1, 1);
        rs1 += __shfl_xor_sync(0xffffffffu, rs1, 2);
        lr0 = lr0 * cor0 + rs0;
        lr1 = lr1 * cor1 + rs1;
#pragma unroll
        for (int j = 0; j < 16; j++) {
            oacc[j][0] *= cor0; oacc[j][1] *= cor0;
            oacc[j][2] *= cor1; oacc[j][3] *= cor1;
        }

#pragma unroll
        for (int kk = 0; kk < 8; kk++) {
            uint32_t pa[4] = { ph[2 * kk][0], ph[2 * kk][1], ph[2 * kk + 1][0], ph[2 * kk + 1][1] };
#pragma unroll
            for (int nb = 0; nb < 8; nb++) {
                uint32_t bb[4];
                int key = kk * 16 + (lane & 7) + (((lane >> 3) & 1) << 3);
                int dc  = nb * 16 + ((lane >> 4) << 3);
                ldsm4t(bb, &vst[key * FSTR + dc]);
                mma16816(oacc[2 * nb],     pa, bb[0], bb[1]);
                mma16816(oacc[2 * nb + 1], pa, bb[2], bb[3]);
            }
        }
        __syncthreads();
    }

    float il0 = 1.0f / lr0, il1 = 1.0f / lr1;
    int r0 = q0w + (lane >> 2), c0 = (lane & 3) * 2;
#pragma unroll
    for (int j = 0; j < 16; j++) {
        __half2 h0 = __floats2half2_rn(oacc[j][0] * il0, oacc[j][1] * il0);
        __half2 h1 = __floats2half2_rn(oacc[j][2] * il1, oacc[j][3] * il1);
        *(__half2*)&Op[(size_t)r0 * DIM + j * 8 + c0] = h0;
        *(__half2*)&Op[(size_t)(r0 + 8) * DIM + j * 8 + c0] = h1;
    }
}

// ---------------- fp32 -> fp16 convert ----------------
__global__ void k_conv(const float2* __restrict__ in, __half2* __restrict__ out, int n2) {
    for (int i = blockIdx.x * 256 + threadIdx.x; i < n2; i += gridDim.x * 256) {
        float2 v = in[i];
        out[i] = __floats2half2_rn(v.x, v.y);
    }
}

// ---------------- launch ----------------
extern "C" void kernel_launch(void* const* d_in, const int* in_sizes, int n_in,
                              void* d_out, int out_size)
{
    const float* x  = (const float*)d_in[0];
    const float* fc = (const float*)d_in[1];
    const float* fs = (const float*)d_in[2];
    const float* wq = (const float*)d_in[3];
    const float* wk = (const float*)d_in[4];
    const float* wv = (const float*)d_in[5];
    const float* wo = (const float*)d_in[6];
    float* out = (float*)d_out;

    cudaFuncSetAttribute(k_proj_rope, cudaFuncAttributeMaxDynamicSharedMemorySize, SMEM_PJ);
    cudaFuncSetAttribute(k_proj_h,    cudaFuncAttributeMaxDynamicSharedMemorySize, SMEM_PJ);
    cudaFuncSetAttribute(k_proj_f,    cudaFuncAttributeMaxDynamicSharedMemorySize, SMEM_PJ);
    cudaFuncSetAttribute(k_flash,     cudaFuncAttributeMaxDynamicSharedMemorySize, SMEM_FL);

    half_t *xh, *wqh, *wkh, *wvh, *woh, *Qh, *Kh, *Vh, *Ah;
    cudaGetSymbolAddress((void**)&xh,  g_xh);
    cudaGetSymbolAddress((void**)&wqh, g_wqh);
    cudaGetSymbolAddress((void**)&wkh, g_wkh);
    cudaGetSymbolAddress((void**)&wvh, g_wvh);
    cudaGetSymbolAddress((void**)&woh, g_woh);
    cudaGetSymbolAddress((void**)&Qh,  g_Qh);
    cudaGetSymbolAddress((void**)&Kh,  g_Kh);
    cudaGetSymbolAddress((void**)&Vh,  g_Vh);
    cudaGetSymbolAddress((void**)&Ah,  g_Ah);

    // 1) converts (no transposes — B consumed in natural [K,N] layout)
    k_conv<<<4096, 256>>>((const float2*)x,  (__half2*)xh,  NTOK * DIM / 2);
    k_conv<<<4096, 256>>>((const float2*)wq, (__half2*)wqh, DIM * DIM / 2);
    k_conv<<<2048, 256>>>((const float2*)wk, (__half2*)wkh, DIM * KVD / 2);
    k_conv<<<2048, 256>>>((const float2*)wv, (__half2*)wvh, DIM * KVD / 2);
    k_conv<<<4096, 256>>>((const float2*)wo, (__half2*)woh, DIM * DIM / 2);

    // 2) projections with fused epilogues (rope for Q/K, fp16 for V)
    k_proj_rope<<<dim3(DIM / 128, NTOK / 128), 256, SMEM_PJ>>>(xh, wqh, Qh, DIM, DIM, DIM, fc, fs);
    k_proj_rope<<<dim3(KVD / 128, NTOK / 128), 256, SMEM_PJ>>>(xh, wkh, Kh, KVD, KVD, DIM, fc, fs);
    k_proj_h<<<dim3(KVD / 128, NTOK / 128), 256, SMEM_PJ>>>(xh, wvh, Vh, KVD, KVD, DIM);

    // 3) fused attention
    k_flash<<<dim3(SEQ / 128, BATCH * NH), 256, SMEM_FL>>>();

    // 4) output projection -> fp32 d_out
    k_proj_f<<<dim3(DIM / 128, DIM / 128), 256, SMEM_PJ>>>(Ah, woh, out, DIM, DIM, DIM);
}

// round 16
// speedup vs baseline: 5.0290x; 1.1037x over previous
#include <cuda_runtime.h>
#include <cuda_fp16.h>
#include <cuda_pipeline.h>
#include <math.h>
#include <stdint.h>

#define BATCH 4
#define SEQ   1024
#define DIM   4096
#define NH    32
#define NKV   8
#define HD    128
#define KVD   (NKV*HD)            // 1024
#define NTOK  (BATCH*SEQ)         // 4096
#define NTOT  (DIM + 2*KVD)       // 6144 fused QKV output cols
#define SCALE 0.08838834764831845f

#define STR  72                   // A smem stride (halves)
#define BSTR 136                  // B smem stride (halves)
#define FSTR 136                  // flash smem stride (halves)

typedef __half half_t;

// ---------------- scratch (device globals) ----------------
__device__ half_t g_xh [(size_t)NTOK * DIM];
__device__ half_t g_wqh[(size_t)DIM * DIM];     // natural [K,N] fp16
__device__ half_t g_wkh[(size_t)DIM * KVD];
__device__ half_t g_wvh[(size_t)DIM * KVD];
__device__ half_t g_woh[(size_t)DIM * DIM];
__device__ half_t g_Qh [(size_t)NTOK * DIM];
__device__ half_t g_Kh [(size_t)NTOK * KVD];
__device__ half_t g_Vh [(size_t)NTOK * KVD];
__device__ half_t g_Ah [(size_t)NTOK * DIM];

// ---------------- mma.sync helpers ----------------
__device__ __forceinline__ void ldsm4(uint32_t* r, const half_t* p) {
    uint32_t a = (uint32_t)__cvta_generic_to_shared(p);
    asm volatile("ldmatrix.sync.aligned.m8n8.x4.shared.b16 {%0,%1,%2,%3}, [%4];"
        : "=r"(r[0]), "=r"(r[1]), "=r"(r[2]), "=r"(r[3]) : "r"(a));
}
__device__ __forceinline__ void ldsm4t(uint32_t* r, const half_t* p) {
    uint32_t a = (uint32_t)__cvta_generic_to_shared(p);
    asm volatile("ldmatrix.sync.aligned.m8n8.x4.trans.shared.b16 {%0,%1,%2,%3}, [%4];"
        : "=r"(r[0]), "=r"(r[1]), "=r"(r[2]), "=r"(r[3]) : "r"(a));
}
__device__ __forceinline__ void mma16816(float* c, const uint32_t* a, uint32_t b0, uint32_t b1) {
    asm volatile("mma.sync.aligned.m16n8k16.row.col.f32.f16.f16.f32 "
        "{%0,%1,%2,%3}, {%4,%5,%6,%7}, {%8,%9}, {%0,%1,%2,%3};"
        : "+f"(c[0]), "+f"(c[1]), "+f"(c[2]), "+f"(c[3])
        : "r"(a[0]), "r"(a[1]), "r"(a[2]), "r"(a[3]), "r"(b0), "r"(b1));
}
__device__ __forceinline__ uint32_t packh2(float a, float b) {
    __half2 h = __floats2half2_rn(a, b);
    return *(uint32_t*)&h;
}

// ---------------- GEMM mainloop (shared by QKV and O kernels) -----------------
// Computes acc[2][8][4] for a 128x128 CTA tile of A[M,K(=4096)] @ B[K,N].
__device__ __forceinline__ void gemm_main(const half_t* __restrict__ A, int lda,
                                          const half_t* __restrict__ B, int ldb,
                                          int bm, int bn, float acc[2][8][4])
{
    extern __shared__ half_t sm[];
    half_t* sA[2] = { sm,                 sm + 128 * STR };
    half_t* sB[2] = { sm + 2 * 128 * STR, sm + 2 * 128 * STR + 64 * BSTR };

    const int tid = threadIdx.x, warp = tid >> 5, lane = tid & 31;
    const int wm = (warp >> 1) * 32;
    const int wn = (warp & 1) * 64;

#pragma unroll
    for (int mi = 0; mi < 2; mi++)
#pragma unroll
        for (int nb = 0; nb < 8; nb++)
#pragma unroll
            for (int e = 0; e < 4; e++) acc[mi][nb][e] = 0.0f;

    auto load_tile = [&](int st, int k0) {
#pragma unroll
        for (int l = 0; l < 4; l++) {
            int idx = l * 256 + tid;
            int r = idx >> 3, c8 = idx & 7;
            __pipeline_memcpy_async(&sA[st][r * STR + c8 * 8],
                                    &A[(size_t)(bm + r) * lda + k0 + c8 * 8], 16);
        }
#pragma unroll
        for (int l = 0; l < 4; l++) {
            int idx = l * 256 + tid;
            int r = idx >> 4, c8 = idx & 15;
            __pipeline_memcpy_async(&sB[st][r * BSTR + c8 * 8],
                                    &B[(size_t)(k0 + r) * ldb + bn + c8 * 8], 16);
        }
    };

    const int nt = DIM / 64;
    load_tile(0, 0);
    __pipeline_commit();

    for (int t = 0; t < nt; t++) {
        if (t + 1 < nt) {
            load_tile((t + 1) & 1, (t + 1) * 64);
            __pipeline_commit();
            __pipeline_wait_prior(1);
        } else {
            __pipeline_wait_prior(0);
        }
        __syncthreads();

        const int st = t & 1;
#pragma unroll
        for (int kk = 0; kk < 64; kk += 16) {
            uint32_t a0[4], a1[4];
            ldsm4(a0, &sA[st][(wm + (lane & 15)) * STR + kk + (lane >> 4) * 8]);
            ldsm4(a1, &sA[st][(wm + 16 + (lane & 15)) * STR + kk + (lane >> 4) * 8]);
#pragma unroll
            for (int nb2 = 0; nb2 < 4; nb2++) {
                uint32_t bb[4];
                int kr = kk + (lane & 7) + (((lane >> 3) & 1) << 3);
                int nc = wn + nb2 * 16 + ((lane >> 4) << 3);
                ldsm4t(bb, &sB[st][kr * BSTR + nc]);
                mma16816(acc[0][2 * nb2],     a0, bb[0], bb[1]);
                mma16816(acc[0][2 * nb2 + 1], a0, bb[2], bb[3]);
                mma16816(acc[1][2 * nb2],     a1, bb[0], bb[1]);
                mma16816(acc[1][2 * nb2 + 1], a1, bb[2], bb[3]);
            }
        }
        __syncthreads();
    }
}

#define SMEM_PJ ((2 * 128 * STR + 2 * 64 * BSTR) * (int)sizeof(half_t))  // 71680 B
#define SMEM_FL (5 * 128 * FSTR * (int)sizeof(half_t))                   // 174080 B

// ---------------- fused QKV projection (one grid over N = 6144) ---------------
__global__ void __launch_bounds__(256, 2) k_qkv(const float* __restrict__ cs,
                                                const float* __restrict__ sn)
{
    const int bm = blockIdx.y * 128;
    const int bng = blockIdx.x * 128;

    // region dispatch (uniform per CTA)
    const half_t* B; int ldb, bn; half_t* C; int ldc; bool rope;
    if (bng < DIM)              { B = g_wqh; ldb = DIM; bn = bng;             C = g_Qh; ldc = DIM; rope = true;  }
    else if (bng < DIM + KVD)   { B = g_wkh; ldb = KVD; bn = bng - DIM;       C = g_Kh; ldc = KVD; rope = true;  }
    else                        { B = g_wvh; ldb = KVD; bn = bng - DIM - KVD; C = g_Vh; ldc = KVD; rope = false; }

    float acc[2][8][4];
    gemm_main(g_xh, DIM, B, ldb, bm, bn, acc);

    const int lane = threadIdx.x & 31, warp = threadIdx.x >> 5;
    const int wm = (warp >> 1) * 32, wn = (warp & 1) * 64;

#pragma unroll
    for (int mi = 0; mi < 2; mi++) {
        int r0 = bm + wm + mi * 16 + (lane >> 2);
#pragma unroll
        for (int nb = 0; nb < 8; nb++) {
            int c = bn + wn + nb * 8 + (lane & 3) * 2;
            float v0 = acc[mi][nb][0], v1 = acc[mi][nb][1];
            float v2 = acc[mi][nb][2], v3 = acc[mi][nb][3];
            if (rope) {
                int i = (c & 127) >> 1;
                int s0 = r0 & (SEQ - 1), s1 = (r0 + 8) & (SEQ - 1);
                float c0 = cs[s0 * 64 + i], z0 = sn[s0 * 64 + i];
                float c1 = cs[s1 * 64 + i], z1 = sn[s1 * 64 + i];
                *(__half2*)&C[(size_t)r0 * ldc + c] =
                    __floats2half2_rn(v0 * c0 - v1 * z0, v0 * z0 + v1 * c0);
                *(__half2*)&C[(size_t)(r0 + 8) * ldc + c] =
                    __floats2half2_rn(v2 * c1 - v3 * z1, v2 * z1 + v3 * c1);
            } else {
                *(__half2*)&C[(size_t)r0 * ldc + c]       = __floats2half2_rn(v0, v1);
                *(__half2*)&C[(size_t)(r0 + 8) * ldc + c] = __floats2half2_rn(v2, v3);
            }
        }
    }
}

// ---------------- output projection -> fp32 ----------------
__global__ void __launch_bounds__(256, 2) k_projo(float* __restrict__ out)
{
    const int bm = blockIdx.y * 128, bn = blockIdx.x * 128;
    float acc[2][8][4];
    gemm_main(g_Ah, DIM, g_woh, DIM, bm, bn, acc);

    const int lane = threadIdx.x & 31, warp = threadIdx.x >> 5;
    const int wm = (warp >> 1) * 32, wn = (warp & 1) * 64;
#pragma unroll
    for (int mi = 0; mi < 2; mi++) {
        int r0 = bm + wm + mi * 16 + (lane >> 2);
#pragma unroll
        for (int nb = 0; nb < 8; nb++) {
            int c = bn + wn + nb * 8 + (lane & 3) * 2;
            *(float2*)&out[(size_t)r0 * DIM + c]       = make_float2(acc[mi][nb][0], acc[mi][nb][1]);
            *(float2*)&out[(size_t)(r0 + 8) * DIM + c] = make_float2(acc[mi][nb][2], acc[mi][nb][3]);
        }
    }
}

// ---------------- fused flash attention (unchanged, proven) ----------------
__global__ void __launch_bounds__(256, 1) k_flash() {
    int z = blockIdx.y, b = z >> 5, h = z & 31, kvh = h >> 2;
    int q0 = blockIdx.x * 128;
    const half_t* Qp = g_Qh + ((size_t)b * SEQ + q0) * DIM + h * HD;
    const half_t* Kp = g_Kh + (size_t)b * SEQ * KVD + kvh * HD;
    const half_t* Vp = g_Vh + (size_t)b * SEQ * KVD + kvh * HD;
    half_t*       Op = g_Ah + ((size_t)b * SEQ + q0) * DIM + h * HD;

    extern __shared__ half_t sm[];
    half_t* sQ = sm;
    half_t* sK = sm + 128 * FSTR;
    half_t* sV = sm + 3 * 128 * FSTR;

    const int tid = threadIdx.x, warp = tid >> 5, lane = tid & 31;
    const int q0w = warp * 16;

    for (int i = tid; i < 128 * 16; i += 256) {
        int r = i >> 4, c = i & 15;
        *(uint4*)&sQ[r * FSTR + c * 8] = *(const uint4*)&Qp[(size_t)r * DIM + c * 8];
    }

    auto loadKV = [&](int st, int t) {
        const half_t* kp = Kp + (size_t)t * 128 * KVD;
        const half_t* vp = Vp + (size_t)t * 128 * KVD;
        half_t* dk = sK + st * 128 * FSTR;
        half_t* dv = sV + st * 128 * FSTR;
#pragma unroll
        for (int l = 0; l < 8; l++) {
            int i = l * 256 + tid;
            int r = i >> 4, c = i & 15;
            __pipeline_memcpy_async(&dk[r * FSTR + c * 8], &kp[(size_t)r * KVD + c * 8], 16);
            __pipeline_memcpy_async(&dv[r * FSTR + c * 8], &vp[(size_t)r * KVD + c * 8], 16);
        }
    };

    loadKV(0, 0);
    __pipeline_commit();
    __syncthreads();

    float oacc[16][4];
#pragma unroll
    for (int j = 0; j < 16; j++)
#pragma unroll
        for (int e = 0; e < 4; e++) oacc[j][e] = 0.0f;
    float mr0 = -1e30f, mr1 = -1e30f, lr0 = 0.0f, lr1 = 0.0f;

    for (int t = 0; t < SEQ / 128; t++) {
        if (t + 1 < SEQ / 128) {
            loadKV((t + 1) & 1, t + 1);
            __pipeline_commit();
            __pipeline_wait_prior(1);
        } else {
            __pipeline_wait_prior(0);
        }
        __syncthreads();
        const half_t* kst = sK + (t & 1) * 128 * FSTR;
        const half_t* vst = sV + (t & 1) * 128 * FSTR;

        float sacc[16][4];
#pragma unroll
        for (int j = 0; j < 16; j++)
#pragma unroll
            for (int e = 0; e < 4; e++) sacc[j][e] = 0.0f;

#pragma unroll
        for (int kd = 0; kd < 8; kd++) {
            uint32_t a[4];
            ldsm4(a, &sQ[(q0w + (lane & 15)) * FSTR + kd * 16 + (lane >> 4) * 8]);
#pragma unroll
            for (int nb = 0; nb < 8; nb++) {
                uint32_t bb[4];
                int key = nb * 16 + (lane & 7) + ((lane >> 4) << 3);
                int dc  = kd * 16 + (((lane >> 3) & 1) << 3);
                ldsm4(bb, &kst[key * FSTR + dc]);
                mma16816(sacc[2 * nb],     a, bb[0], bb[1]);
                mma16816(sacc[2 * nb + 1], a, bb[2], bb[3]);
            }
        }

        float tm0 = -1e30f, tm1 = -1e30f;
#pragma unroll
        for (int j = 0; j < 16; j++) {
            sacc[j][0] *= SCALE; sacc[j][1] *= SCALE;
            sacc[j][2] *= SCALE; sacc[j][3] *= SCALE;
            tm0 = fmaxf(tm0, fmaxf(sacc[j][0], sacc[j][1]));
            tm1 = fmaxf(tm1, fmaxf(sacc[j][2], sacc[j][3]));
        }
        tm0 = fmaxf(tm0, __shfl_xor_sync(0xffffffffu, tm0, 1));
        tm0 = fmaxf(tm0, __shfl_xor_sync(0xffffffffu, tm0, 2));
        tm1 = fmaxf(tm1, __shfl_xor_sync(0xffffffffu, tm1, 1));
        tm1 = fmaxf(tm1, __shfl_xor_sync(0xffffffffu, tm1, 2));
        float mn0 = fmaxf(mr0, tm0), mn1 = fmaxf(mr1, tm1);
        float cor0 = __expf(mr0 - mn0), cor1 = __expf(mr1 - mn1);
        mr0 = mn0; mr1 = mn1;

        uint32_t ph[16][2];
        float rs0 = 0.0f, rs1 = 0.0f;
#pragma unroll
        for (int j = 0; j < 16; j++) {
            float e0 = __expf(sacc[j][0] - mn0), e1 = __expf(sacc[j][1] - mn0);
            float e2 = __expf(sacc[j][2] - mn1), e3 = __expf(sacc[j][3] - mn1);
            rs0 += e0 + e1; rs1 += e2 + e3;
            ph[j][0] = packh2(e0, e1);
            ph[j][1] = packh2(e2, e3);
        }
        rs0 += __shfl_xor_sync(0xffffffffu, rs0, 1);
        rs0 += __shfl_xor_sync(0xffffffffu, rs0, 2);
        rs1 += __shfl_xor_sync(0xffffffffu, rs1, 1);
        rs1 += __shfl_xor_sync(0xffffffffu, rs1, 2);
        lr0 = lr0 * cor0 + rs0;
        lr1 = lr1 * cor1 + rs1;
#pragma unroll
        for (int j = 0; j < 16; j++) {
            oacc[j][0] *= cor0; oacc[j][1] *= cor0;
            oacc[j][2] *= cor1; oacc[j][3] *= cor1;
        }

#pragma unroll
        for (int kk = 0; kk < 8; kk++) {
            uint32_t pa[4] = { ph[2 * kk][0], ph[2 * kk][1], ph[2 * kk + 1][0], ph[2 * kk + 1][1] };
#pragma unroll
            for (int nb = 0; nb < 8; nb++) {
                uint32_t bb[4];
                int key = kk * 16 + (lane & 7) + (((lane >> 3) & 1) << 3);
                int dc  = nb * 16 + ((lane >> 4) << 3);
                ldsm4t(bb, &vst[key * FSTR + dc]);
                mma16816(oacc[2 * nb],     pa, bb[0], bb[1]);
                mma16816(oacc[2 * nb + 1], pa, bb[2], bb[3]);
            }
        }
        __syncthreads();
    }

    float il0 = 1.0f / lr0, il1 = 1.0f / lr1;
    int r0 = q0w + (lane >> 2), c0 = (lane & 3) * 2;
#pragma unroll
    for (int j = 0; j < 16; j++) {
        __half2 h0 = __floats2half2_rn(oacc[j][0] * il0, oacc[j][1] * il0);
        __half2 h1 = __floats2half2_rn(oacc[j][2] * il1, oacc[j][3] * il1);
        *(__half2*)&Op[(size_t)r0 * DIM + j * 8 + c0] = h0;
        *(__half2*)&Op[(size_t)(r0 + 8) * DIM + j * 8 + c0] = h1;
    }
}

// ---------------- fp32 -> fp16 convert (wide: 8 halves / iter) ----------------
__global__ void k_conv(const float4* __restrict__ in, uint4* __restrict__ out, int n8) {
    for (int i = blockIdx.x * 256 + threadIdx.x; i < n8; i += gridDim.x * 256) {
        float4 a = in[2 * i], b = in[2 * i + 1];
        __half2 h0 = __floats2half2_rn(a.x, a.y);
        __half2 h1 = __floats2half2_rn(a.z, a.w);
        __half2 h2 = __floats2half2_rn(b.x, b.y);
        __half2 h3 = __floats2half2_rn(b.z, b.w);
        uint4 o;
        o.x = *(uint32_t*)&h0; o.y = *(uint32_t*)&h1;
        o.z = *(uint32_t*)&h2; o.w = *(uint32_t*)&h3;
        out[i] = o;
    }
}

// ---------------- launch ----------------
extern "C" void kernel_launch(void* const* d_in, const int* in_sizes, int n_in,
                              void* d_out, int out_size)
{
    const float* x  = (const float*)d_in[0];
    const float* fc = (const float*)d_in[1];
    const float* fs = (const float*)d_in[2];
    const float* wq = (const float*)d_in[3];
    const float* wk = (const float*)d_in[4];
    const float* wv = (const float*)d_in[5];
    const float* wo = (const float*)d_in[6];
    float* out = (float*)d_out;

    cudaFuncSetAttribute(k_qkv,   cudaFuncAttributeMaxDynamicSharedMemorySize, SMEM_PJ);
    cudaFuncSetAttribute(k_projo, cudaFuncAttributeMaxDynamicSharedMemorySize, SMEM_PJ);
    cudaFuncSetAttribute(k_flash, cudaFuncAttributeMaxDynamicSharedMemorySize, SMEM_FL);

    half_t *xh, *wqh, *wkh, *wvh, *woh;
    cudaGetSymbolAddress((void**)&xh,  g_xh);
    cudaGetSymbolAddress((void**)&wqh, g_wqh);
    cudaGetSymbolAddress((void**)&wkh, g_wkh);
    cudaGetSymbolAddress((void**)&wvh, g_wvh);
    cudaGetSymbolAddress((void**)&woh, g_woh);

    // 1) converts (natural layouts; no transposes)
    k_conv<<<1024, 256>>>((const float4*)x,  (uint4*)xh,  NTOK * DIM / 8);
    k_conv<<<1024, 256>>>((const float4*)wq, (uint4*)wqh, DIM * DIM / 8);
    k_conv<<<512,  256>>>((const float4*)wk, (uint4*)wkh, DIM * KVD / 8);
    k_conv<<<512,  256>>>((const float4*)wv, (uint4*)wvh, DIM * KVD / 8);
    k_conv<<<1024, 256>>>((const float4*)wo, (uint4*)woh, DIM * DIM / 8);

    // 2) fused QKV projection (rope fused for Q/K)
    k_qkv<<<dim3(NTOT / 128, NTOK / 128), 256, SMEM_PJ>>>(fc, fs);

    // 3) fused attention
    k_flash<<<dim3(SEQ / 128, BATCH * NH), 256, SMEM_FL>>>();

    // 4) output projection -> fp32 d_out
    k_projo<<<dim3(DIM / 128, DIM / 128), 256, SMEM_PJ>>>(out);
}